// round 4
// baseline (speedup 1.0000x reference)
#include <cuda_runtime.h>
#include <math.h>

#define Bb 8
#define Cc 512
#define Ll 2048
#define CQq 128

// Static device scratch (allocation-free rule: __device__ globals).
__device__ float g_q[Bb * CQq * Ll];        // 8 MiB
__device__ float g_k[Bb * CQq * Ll];        // 8 MiB
__device__ float g_v[(size_t)Bb * Cc * Ll]; // 32 MiB (gamma!=0 path only)
__device__ float g_att[(size_t)Bb * Ll * Ll];     // 128 MiB fallback
__device__ float g_outbuf[(size_t)Bb * Cc * Ll];  // 32 MiB fallback

// ---------------------------------------------------------------------------
// Generic 1x1 conv (channel GEMM): out[b,m,n] = sum_k W[m,k]*x[b,k,n] + bias[m]
// Tile 128x128xBK8, 256 threads, 8x8 per thread.
// GATE=1: run only when gamma[0] != 0 (v projection on the dead path).
// ---------------------------------------------------------------------------
template <int GATE>
__global__ __launch_bounds__(256)
void conv1x1_kernel(const float* __restrict__ W, const float* __restrict__ bias,
                    const float* __restrict__ x, float* __restrict__ out,
                    int M, const float* __restrict__ gamma)
{
    if (GATE) { if (gamma[0] == 0.0f) return; }
    const int b  = blockIdx.z;
    const int m0 = blockIdx.y * 128;
    const int n0 = blockIdx.x * 128;

    __shared__ float As[8][128];   // As[k][m]
    __shared__ float Bs[8][128];   // Bs[k][n]

    const int tid = threadIdx.x;
    const int tx = tid % 16, ty = tid / 16;

    const float* xb = x + (size_t)b * Cc * Ll;

    const int aRow = tid >> 1;          // 0..127 (m)
    const int aCol = (tid & 1) * 4;     // 0 / 4  (k)
    const int bRow = tid >> 5;          // 0..7   (k)
    const int bCol = (tid & 31) * 4;    // 0..124 (n)

    float acc[8][8];
    #pragma unroll
    for (int i = 0; i < 8; i++)
        #pragma unroll
        for (int j = 0; j < 8; j++) acc[i][j] = 0.0f;

    for (int k0 = 0; k0 < Cc; k0 += 8) {
        float4 a = *(const float4*)&W[(size_t)(m0 + aRow) * Cc + k0 + aCol];
        As[aCol + 0][aRow] = a.x;
        As[aCol + 1][aRow] = a.y;
        As[aCol + 2][aRow] = a.z;
        As[aCol + 3][aRow] = a.w;
        *(float4*)&Bs[bRow][bCol] =
            *(const float4*)&xb[(size_t)(k0 + bRow) * Ll + n0 + bCol];
        __syncthreads();

        #pragma unroll
        for (int k = 0; k < 8; k++) {
            float rm[8], rn[8];
            #pragma unroll
            for (int i = 0; i < 8; i++) rm[i] = As[k][ty * 8 + i];
            #pragma unroll
            for (int j = 0; j < 8; j++) rn[j] = Bs[k][tx * 8 + j];
            #pragma unroll
            for (int i = 0; i < 8; i++)
                #pragma unroll
                for (int j = 0; j < 8; j++)
                    acc[i][j] = fmaf(rm[i], rn[j], acc[i][j]);
        }
        __syncthreads();
    }

    float* ob = out + (size_t)b * M * Ll;
    #pragma unroll
    for (int i = 0; i < 8; i++) {
        const int m = m0 + ty * 8 + i;
        const float bb = bias[m];
        float* po = ob + (size_t)m * Ll + n0 + tx * 8;
        float4 v0 = make_float4(acc[i][0] + bb, acc[i][1] + bb,
                                acc[i][2] + bb, acc[i][3] + bb);
        float4 v1 = make_float4(acc[i][4] + bb, acc[i][5] + bb,
                                acc[i][6] + bb, acc[i][7] + bb);
        *(float4*)po       = v0;
        *(float4*)(po + 4) = v1;
    }
}

// ---------------------------------------------------------------------------
// energy[b,i,j] = sum_d q[b,d,i] * k[b,d,j]   (TN GEMM, K = CQ = 128)
// ---------------------------------------------------------------------------
__global__ __launch_bounds__(256)
void energy_kernel(float* __restrict__ E)
{
    const int b  = blockIdx.z;
    const int i0 = blockIdx.y * 128;
    const int j0 = blockIdx.x * 128;

    __shared__ float Qs[8][128];   // Qs[d][i]
    __shared__ float Ks[8][128];   // Ks[d][j]

    const int tid = threadIdx.x;
    const int tx = tid % 16, ty = tid / 16;
    const int lRow = tid >> 5;          // 0..7  (d)
    const int lCol = (tid & 31) * 4;    // 0..124

    const float* qb = g_q + (size_t)b * CQq * Ll;
    const float* kb = g_k + (size_t)b * CQq * Ll;

    float acc[8][8];
    #pragma unroll
    for (int i = 0; i < 8; i++)
        #pragma unroll
        for (int j = 0; j < 8; j++) acc[i][j] = 0.0f;

    for (int d0 = 0; d0 < CQq; d0 += 8) {
        *(float4*)&Qs[lRow][lCol] =
            *(const float4*)&qb[(size_t)(d0 + lRow) * Ll + i0 + lCol];
        *(float4*)&Ks[lRow][lCol] =
            *(const float4*)&kb[(size_t)(d0 + lRow) * Ll + j0 + lCol];
        __syncthreads();

        #pragma unroll
        for (int k = 0; k < 8; k++) {
            float rm[8], rn[8];
            #pragma unroll
            for (int i = 0; i < 8; i++) rm[i] = Qs[k][ty * 8 + i];
            #pragma unroll
            for (int j = 0; j < 8; j++) rn[j] = Ks[k][tx * 8 + j];
            #pragma unroll
            for (int i = 0; i < 8; i++)
                #pragma unroll
                for (int j = 0; j < 8; j++)
                    acc[i][j] = fmaf(rm[i], rn[j], acc[i][j]);
        }
        __syncthreads();
    }

    float* eb = E + (size_t)b * Ll * Ll;
    #pragma unroll
    for (int i = 0; i < 8; i++) {
        float* po = eb + (size_t)(i0 + ty * 8 + i) * Ll + j0 + tx * 8;
        *(float4*)po       = make_float4(acc[i][0], acc[i][1], acc[i][2], acc[i][3]);
        *(float4*)(po + 4) = make_float4(acc[i][4], acc[i][5], acc[i][6], acc[i][7]);
    }
}

// ---------------------------------------------------------------------------
// In-place row softmax over last axis. One block (256 thr) per row of 2048.
// ---------------------------------------------------------------------------
__global__ __launch_bounds__(256)
void softmax_kernel(float* __restrict__ att)
{
    const size_t row = blockIdx.x;          // b*L + i
    float* p = att + row * (size_t)Ll;
    const int tid = threadIdx.x;

    float vals[8];
    float m = -INFINITY;
    #pragma unroll
    for (int j = 0; j < 8; j++) {
        vals[j] = p[tid + j * 256];
        m = fmaxf(m, vals[j]);
    }
    __shared__ float red[256];
    red[tid] = m;
    __syncthreads();
    #pragma unroll
    for (int s = 128; s > 0; s >>= 1) {
        if (tid < s) red[tid] = fmaxf(red[tid], red[tid + s]);
        __syncthreads();
    }
    m = red[0];
    __syncthreads();

    float sum = 0.0f;
    #pragma unroll
    for (int j = 0; j < 8; j++) {
        vals[j] = expf(vals[j] - m);
        sum += vals[j];
    }
    red[tid] = sum;
    __syncthreads();
    #pragma unroll
    for (int s = 128; s > 0; s >>= 1) {
        if (tid < s) red[tid] += red[tid + s];
        __syncthreads();
    }
    const float inv = 1.0f / red[0];
    #pragma unroll
    for (int j = 0; j < 8; j++) p[tid + j * 256] = vals[j] * inv;
}

// ---------------------------------------------------------------------------
// gamma == 0 fast path: out = x  (vectorized copy). Gated on gamma[0]==0.
// ---------------------------------------------------------------------------
__global__ __launch_bounds__(256)
void copy_x_kernel(const float* __restrict__ x, float* __restrict__ out,
                   const float* __restrict__ gamma)
{
    if (gamma[0] != 0.0f) return;
    const size_t idx = ((size_t)blockIdx.x * 256 + threadIdx.x) * 4;
    *(float4*)&out[idx] = *(const float4*)&x[idx];
}

// ---------------------------------------------------------------------------
// gamma != 0 path: out[b,c,i] = gamma * sum_j v[b,c,j]*att[b,i,j] + x[b,c,i]
// (A * B^T tiled GEMM, K = L = 2048). Gated on gamma[0]!=0.
// ---------------------------------------------------------------------------
__global__ __launch_bounds__(256)
void outgemm_kernel(const float* __restrict__ att, const float* __restrict__ x,
                    float* __restrict__ out, const float* __restrict__ gamma)
{
    const float g = gamma[0];
    if (g == 0.0f) return;
    const int b  = blockIdx.z;
    const int c0 = blockIdx.y * 128;
    const int i0 = blockIdx.x * 128;

    __shared__ float Vs[8][128];   // Vs[j][c]
    __shared__ float Ts[8][128];   // Ts[j][i]

    const int tid = threadIdx.x;
    const int tx = tid % 16, ty = tid / 16;
    const int aRow = tid >> 1;        // 0..127
    const int aCol = (tid & 1) * 4;   // 0 / 4 (j)

    const float* vb = g_v + (size_t)b * Cc * Ll;
    const float* ab = att + (size_t)b * Ll * Ll;

    float acc[8][8];
    #pragma unroll
    for (int i = 0; i < 8; i++)
        #pragma unroll
        for (int j = 0; j < 8; j++) acc[i][j] = 0.0f;

    for (int j0 = 0; j0 < Ll; j0 += 8) {
        float4 a = *(const float4*)&vb[(size_t)(c0 + aRow) * Ll + j0 + aCol];
        Vs[aCol + 0][aRow] = a.x;
        Vs[aCol + 1][aRow] = a.y;
        Vs[aCol + 2][aRow] = a.z;
        Vs[aCol + 3][aRow] = a.w;
        float4 t = *(const float4*)&ab[(size_t)(i0 + aRow) * Ll + j0 + aCol];
        Ts[aCol + 0][aRow] = t.x;
        Ts[aCol + 1][aRow] = t.y;
        Ts[aCol + 2][aRow] = t.z;
        Ts[aCol + 3][aRow] = t.w;
        __syncthreads();

        #pragma unroll
        for (int k = 0; k < 8; k++) {
            float rm[8], rn[8];
            #pragma unroll
            for (int i = 0; i < 8; i++) rm[i] = Vs[k][ty * 8 + i];
            #pragma unroll
            for (int j = 0; j < 8; j++) rn[j] = Ts[k][tx * 8 + j];
            #pragma unroll
            for (int i = 0; i < 8; i++)
                #pragma unroll
                for (int j = 0; j < 8; j++)
                    acc[i][j] = fmaf(rm[i], rn[j], acc[i][j]);
        }
        __syncthreads();
    }

    #pragma unroll
    for (int i = 0; i < 8; i++) {
        const size_t off = (size_t)b * Cc * Ll + (size_t)(c0 + ty * 8 + i) * Ll
                         + i0 + tx * 8;
        #pragma unroll
        for (int j = 0; j < 8; j++)
            out[off + j] = g * acc[i][j] + x[off + j];
    }
}

// ---------------------------------------------------------------------------
extern "C" void kernel_launch(void* const* d_in, const int* in_sizes, int n_in,
                              void* d_out, int out_size)
{
    (void)in_sizes; (void)n_in;
    const float* x     = (const float*)d_in[0];
    const float* q_w   = (const float*)d_in[1];
    const float* q_b   = (const float*)d_in[2];
    const float* k_w   = (const float*)d_in[3];
    const float* k_b   = (const float*)d_in[4];
    const float* v_w   = (const float*)d_in[5];
    const float* v_b   = (const float*)d_in[6];
    const float* gamma = (const float*)d_in[7];

    const size_t BCL = (size_t)Bb * Cc * Ll;        // 8388608
    const size_t BLL = (size_t)Bb * Ll * Ll;        // 33554432

    float* out_ptr;
    float* att_ptr;
    if ((size_t)out_size >= BCL + BLL) {
        out_ptr = (float*)d_out;
        att_ptr = (float*)d_out + BCL;
    } else if ((size_t)out_size == BLL) {
        cudaGetSymbolAddress((void**)&out_ptr, g_outbuf);
        att_ptr = (float*)d_out;
    } else {
        out_ptr = (float*)d_out;
        cudaGetSymbolAddress((void**)&att_ptr, g_att);
    }
    float* qbuf; cudaGetSymbolAddress((void**)&qbuf, g_q);
    float* kbuf; cudaGetSymbolAddress((void**)&kbuf, g_k);
    float* vbuf; cudaGetSymbolAddress((void**)&vbuf, g_v);

    dim3 blk(256);

    // q and k projections (ungated)
    conv1x1_kernel<0><<<dim3(Ll / 128, CQq / 128, Bb), blk>>>(q_w, q_b, x, qbuf, CQq, gamma);
    conv1x1_kernel<0><<<dim3(Ll / 128, CQq / 128, Bb), blk>>>(k_w, k_b, x, kbuf, CQq, gamma);

    // energy -> attention region, softmax in place
    energy_kernel<<<dim3(Ll / 128, Ll / 128, Bb), blk>>>(att_ptr);
    softmax_kernel<<<dim3(Bb * Ll), blk>>>(att_ptr);

    // out path: gamma==0 -> copy; gamma!=0 -> v conv + out GEMM
    copy_x_kernel<<<dim3((unsigned)(BCL / (256 * 4))), blk>>>(x, out_ptr, gamma);
    conv1x1_kernel<1><<<dim3(Ll / 128, Cc / 128, Bb), blk>>>(v_w, v_b, x, vbuf, Cc, gamma);
    outgemm_kernel<<<dim3(Ll / 128, Cc / 128, Bb), blk>>>(att_ptr, x, out_ptr, gamma);
}

// round 5
// speedup vs baseline: 1.0056x; 1.0056x over previous
#include <cuda_runtime.h>
#include <math.h>

#define Bb 8
#define Cc 512
#define Ll 2048
#define CQq 128

// Static device scratch (allocation-free rule: __device__ globals).
__device__ float g_q[Bb * CQq * Ll];        // 8 MiB
__device__ float g_k[Bb * CQq * Ll];        // 8 MiB
__device__ float g_v[(size_t)Bb * Cc * Ll]; // 32 MiB (gamma!=0 path only)
__device__ float g_att[(size_t)Bb * Ll * Ll];     // 128 MiB fallback
__device__ float g_outbuf[(size_t)Bb * Cc * Ll];  // 32 MiB fallback

// ---------------------------------------------------------------------------
// Generic 1x1 conv (channel GEMM): out[b,m,n] = sum_k W[m,k]*x[b,k,n] + bias[m]
// Tile 128x128xBK8, 256 threads, 8x8 per thread.
// GATE=1: run only when gamma[0] != 0 (v projection on the dead path).
// ---------------------------------------------------------------------------
template <int GATE>
__global__ __launch_bounds__(256)
void conv1x1_kernel(const float* __restrict__ W, const float* __restrict__ bias,
                    const float* __restrict__ x, float* __restrict__ out,
                    int M, const float* __restrict__ gamma)
{
    if (GATE) { if (gamma[0] == 0.0f) return; }
    const int b  = blockIdx.z;
    const int m0 = blockIdx.y * 128;
    const int n0 = blockIdx.x * 128;

    __shared__ float As[8][128];   // As[k][m]
    __shared__ float Bs[8][128];   // Bs[k][n]

    const int tid = threadIdx.x;
    const int tx = tid % 16, ty = tid / 16;

    const float* xb = x + (size_t)b * Cc * Ll;

    const int aRow = tid >> 1;          // 0..127 (m)
    const int aCol = (tid & 1) * 4;     // 0 / 4  (k)
    const int bRow = tid >> 5;          // 0..7   (k)
    const int bCol = (tid & 31) * 4;    // 0..124 (n)

    float acc[8][8];
    #pragma unroll
    for (int i = 0; i < 8; i++)
        #pragma unroll
        for (int j = 0; j < 8; j++) acc[i][j] = 0.0f;

    for (int k0 = 0; k0 < Cc; k0 += 8) {
        float4 a = *(const float4*)&W[(size_t)(m0 + aRow) * Cc + k0 + aCol];
        As[aCol + 0][aRow] = a.x;
        As[aCol + 1][aRow] = a.y;
        As[aCol + 2][aRow] = a.z;
        As[aCol + 3][aRow] = a.w;
        *(float4*)&Bs[bRow][bCol] =
            *(const float4*)&xb[(size_t)(k0 + bRow) * Ll + n0 + bCol];
        __syncthreads();

        #pragma unroll
        for (int k = 0; k < 8; k++) {
            float rm[8], rn[8];
            #pragma unroll
            for (int i = 0; i < 8; i++) rm[i] = As[k][ty * 8 + i];
            #pragma unroll
            for (int j = 0; j < 8; j++) rn[j] = Bs[k][tx * 8 + j];
            #pragma unroll
            for (int i = 0; i < 8; i++)
                #pragma unroll
                for (int j = 0; j < 8; j++)
                    acc[i][j] = fmaf(rm[i], rn[j], acc[i][j]);
        }
        __syncthreads();
    }

    float* ob = out + (size_t)b * M * Ll;
    #pragma unroll
    for (int i = 0; i < 8; i++) {
        const int m = m0 + ty * 8 + i;
        const float bb = bias[m];
        float* po = ob + (size_t)m * Ll + n0 + tx * 8;
        float4 v0 = make_float4(acc[i][0] + bb, acc[i][1] + bb,
                                acc[i][2] + bb, acc[i][3] + bb);
        float4 v1 = make_float4(acc[i][4] + bb, acc[i][5] + bb,
                                acc[i][6] + bb, acc[i][7] + bb);
        *(float4*)po       = v0;
        *(float4*)(po + 4) = v1;
    }
}

// ---------------------------------------------------------------------------
// energy[b,i,j] = sum_d q[b,d,i] * k[b,d,j]   (TN GEMM, K = CQ = 128)
// ---------------------------------------------------------------------------
__global__ __launch_bounds__(256)
void energy_kernel(float* __restrict__ E)
{
    const int b  = blockIdx.z;
    const int i0 = blockIdx.y * 128;
    const int j0 = blockIdx.x * 128;

    __shared__ float Qs[8][128];   // Qs[d][i]
    __shared__ float Ks[8][128];   // Ks[d][j]

    const int tid = threadIdx.x;
    const int tx = tid % 16, ty = tid / 16;
    const int lRow = tid >> 5;          // 0..7  (d)
    const int lCol = (tid & 31) * 4;    // 0..124

    const float* qb = g_q + (size_t)b * CQq * Ll;
    const float* kb = g_k + (size_t)b * CQq * Ll;

    float acc[8][8];
    #pragma unroll
    for (int i = 0; i < 8; i++)
        #pragma unroll
        for (int j = 0; j < 8; j++) acc[i][j] = 0.0f;

    for (int d0 = 0; d0 < CQq; d0 += 8) {
        *(float4*)&Qs[lRow][lCol] =
            *(const float4*)&qb[(size_t)(d0 + lRow) * Ll + i0 + lCol];
        *(float4*)&Ks[lRow][lCol] =
            *(const float4*)&kb[(size_t)(d0 + lRow) * Ll + j0 + lCol];
        __syncthreads();

        #pragma unroll
        for (int k = 0; k < 8; k++) {
            float rm[8], rn[8];
            #pragma unroll
            for (int i = 0; i < 8; i++) rm[i] = Qs[k][ty * 8 + i];
            #pragma unroll
            for (int j = 0; j < 8; j++) rn[j] = Ks[k][tx * 8 + j];
            #pragma unroll
            for (int i = 0; i < 8; i++)
                #pragma unroll
                for (int j = 0; j < 8; j++)
                    acc[i][j] = fmaf(rm[i], rn[j], acc[i][j]);
        }
        __syncthreads();
    }

    float* eb = E + (size_t)b * Ll * Ll;
    #pragma unroll
    for (int i = 0; i < 8; i++) {
        float* po = eb + (size_t)(i0 + ty * 8 + i) * Ll + j0 + tx * 8;
        *(float4*)po       = make_float4(acc[i][0], acc[i][1], acc[i][2], acc[i][3]);
        *(float4*)(po + 4) = make_float4(acc[i][4], acc[i][5], acc[i][6], acc[i][7]);
    }
}

// ---------------------------------------------------------------------------
// In-place row softmax over last axis. One block (256 thr) per row of 2048.
// ---------------------------------------------------------------------------
__global__ __launch_bounds__(256)
void softmax_kernel(float* __restrict__ att)
{
    const size_t row = blockIdx.x;          // b*L + i
    float* p = att + row * (size_t)Ll;
    const int tid = threadIdx.x;

    float vals[8];
    float m = -INFINITY;
    #pragma unroll
    for (int j = 0; j < 8; j++) {
        vals[j] = p[tid + j * 256];
        m = fmaxf(m, vals[j]);
    }
    __shared__ float red[256];
    red[tid] = m;
    __syncthreads();
    #pragma unroll
    for (int s = 128; s > 0; s >>= 1) {
        if (tid < s) red[tid] = fmaxf(red[tid], red[tid + s]);
        __syncthreads();
    }
    m = red[0];
    __syncthreads();

    float sum = 0.0f;
    #pragma unroll
    for (int j = 0; j < 8; j++) {
        vals[j] = expf(vals[j] - m);
        sum += vals[j];
    }
    red[tid] = sum;
    __syncthreads();
    #pragma unroll
    for (int s = 128; s > 0; s >>= 1) {
        if (tid < s) red[tid] += red[tid + s];
        __syncthreads();
    }
    const float inv = 1.0f / red[0];
    #pragma unroll
    for (int j = 0; j < 8; j++) p[tid + j * 256] = vals[j] * inv;
}

// ---------------------------------------------------------------------------
// gamma == 0 fast path: out = x  (vectorized copy). Gated on gamma[0]==0.
// ---------------------------------------------------------------------------
__global__ __launch_bounds__(256)
void copy_x_kernel(const float* __restrict__ x, float* __restrict__ out,
                   const float* __restrict__ gamma)
{
    if (gamma[0] != 0.0f) return;
    const size_t idx = ((size_t)blockIdx.x * 256 + threadIdx.x) * 4;
    *(float4*)&out[idx] = *(const float4*)&x[idx];
}

// ---------------------------------------------------------------------------
// gamma != 0 path: out[b,c,i] = gamma * sum_j v[b,c,j]*att[b,i,j] + x[b,c,i]
// (A * B^T tiled GEMM, K = L = 2048). Gated on gamma[0]!=0.
// ---------------------------------------------------------------------------
__global__ __launch_bounds__(256)
void outgemm_kernel(const float* __restrict__ att, const float* __restrict__ x,
                    float* __restrict__ out, const float* __restrict__ gamma)
{
    const float g = gamma[0];
    if (g == 0.0f) return;
    const int b  = blockIdx.z;
    const int c0 = blockIdx.y * 128;
    const int i0 = blockIdx.x * 128;

    __shared__ float Vs[8][128];   // Vs[j][c]
    __shared__ float Ts[8][128];   // Ts[j][i]

    const int tid = threadIdx.x;
    const int tx = tid % 16, ty = tid / 16;
    const int aRow = tid >> 1;        // 0..127
    const int aCol = (tid & 1) * 4;   // 0 / 4 (j)

    const float* vb = g_v + (size_t)b * Cc * Ll;
    const float* ab = att + (size_t)b * Ll * Ll;

    float acc[8][8];
    #pragma unroll
    for (int i = 0; i < 8; i++)
        #pragma unroll
        for (int j = 0; j < 8; j++) acc[i][j] = 0.0f;

    for (int j0 = 0; j0 < Ll; j0 += 8) {
        float4 a = *(const float4*)&vb[(size_t)(c0 + aRow) * Ll + j0 + aCol];
        Vs[aCol + 0][aRow] = a.x;
        Vs[aCol + 1][aRow] = a.y;
        Vs[aCol + 2][aRow] = a.z;
        Vs[aCol + 3][aRow] = a.w;
        float4 t = *(const float4*)&ab[(size_t)(i0 + aRow) * Ll + j0 + aCol];
        Ts[aCol + 0][aRow] = t.x;
        Ts[aCol + 1][aRow] = t.y;
        Ts[aCol + 2][aRow] = t.z;
        Ts[aCol + 3][aRow] = t.w;
        __syncthreads();

        #pragma unroll
        for (int k = 0; k < 8; k++) {
            float rm[8], rn[8];
            #pragma unroll
            for (int i = 0; i < 8; i++) rm[i] = Vs[k][ty * 8 + i];
            #pragma unroll
            for (int j = 0; j < 8; j++) rn[j] = Ts[k][tx * 8 + j];
            #pragma unroll
            for (int i = 0; i < 8; i++)
                #pragma unroll
                for (int j = 0; j < 8; j++)
                    acc[i][j] = fmaf(rm[i], rn[j], acc[i][j]);
        }
        __syncthreads();
    }

    #pragma unroll
    for (int i = 0; i < 8; i++) {
        const size_t off = (size_t)b * Cc * Ll + (size_t)(c0 + ty * 8 + i) * Ll
                         + i0 + tx * 8;
        #pragma unroll
        for (int j = 0; j < 8; j++)
            out[off + j] = g * acc[i][j] + x[off + j];
    }
}

// ---------------------------------------------------------------------------
extern "C" void kernel_launch(void* const* d_in, const int* in_sizes, int n_in,
                              void* d_out, int out_size)
{
    (void)in_sizes; (void)n_in;
    const float* x     = (const float*)d_in[0];
    const float* q_w   = (const float*)d_in[1];
    const float* q_b   = (const float*)d_in[2];
    const float* k_w   = (const float*)d_in[3];
    const float* k_b   = (const float*)d_in[4];
    const float* v_w   = (const float*)d_in[5];
    const float* v_b   = (const float*)d_in[6];
    const float* gamma = (const float*)d_in[7];

    const size_t BCL = (size_t)Bb * Cc * Ll;        // 8388608
    const size_t BLL = (size_t)Bb * Ll * Ll;        // 33554432

    float* out_ptr;
    float* att_ptr;
    if ((size_t)out_size >= BCL + BLL) {
        out_ptr = (float*)d_out;
        att_ptr = (float*)d_out + BCL;
    } else if ((size_t)out_size == BLL) {
        cudaGetSymbolAddress((void**)&out_ptr, g_outbuf);
        att_ptr = (float*)d_out;
    } else {
        out_ptr = (float*)d_out;
        cudaGetSymbolAddress((void**)&att_ptr, g_att);
    }
    float* qbuf; cudaGetSymbolAddress((void**)&qbuf, g_q);
    float* kbuf; cudaGetSymbolAddress((void**)&kbuf, g_k);
    float* vbuf; cudaGetSymbolAddress((void**)&vbuf, g_v);

    dim3 blk(256);

    // q and k projections (ungated)
    conv1x1_kernel<0><<<dim3(Ll / 128, CQq / 128, Bb), blk>>>(q_w, q_b, x, qbuf, CQq, gamma);
    conv1x1_kernel<0><<<dim3(Ll / 128, CQq / 128, Bb), blk>>>(k_w, k_b, x, kbuf, CQq, gamma);

    // energy -> attention region, softmax in place
    energy_kernel<<<dim3(Ll / 128, Ll / 128, Bb), blk>>>(att_ptr);
    softmax_kernel<<<dim3(Bb * Ll), blk>>>(att_ptr);

    // out path: gamma==0 -> copy; gamma!=0 -> v conv + out GEMM
    copy_x_kernel<<<dim3((unsigned)(BCL / (256 * 4))), blk>>>(x, out_ptr, gamma);
    conv1x1_kernel<1><<<dim3(Ll / 128, Cc / 128, Bb), blk>>>(v_w, v_b, x, vbuf, Cc, gamma);
    outgemm_kernel<<<dim3(Ll / 128, Cc / 128, Bb), blk>>>(att_ptr, x, out_ptr, gamma);
}

// round 7
// speedup vs baseline: 1.3207x; 1.3134x over previous
#include <cuda_runtime.h>
#include <cuda_bf16.h>
#include <stdint.h>
#include <math.h>

#define Bb 8
#define Cc 512
#define Ll 2048
#define CQq 128

// Static device scratch (allocation-free rule: __device__ globals).
__device__ __nv_bfloat16 g_qhi[(size_t)Bb * Ll * CQq];   // [b][pos][d] 4 MiB
__device__ __nv_bfloat16 g_qlo[(size_t)Bb * Ll * CQq];
__device__ __nv_bfloat16 g_khi[(size_t)Bb * Ll * CQq];
__device__ __nv_bfloat16 g_klo[(size_t)Bb * Ll * CQq];
__device__ float g_v[(size_t)Bb * Cc * Ll];              // gamma!=0 path only
__device__ float g_att[(size_t)Bb * Ll * Ll];            // fallback
__device__ float g_outbuf[(size_t)Bb * Cc * Ll];         // fallback

// ---------------------------------------------------------------------------
// q/k 1x1 conv: out[b,m,n] = sum_k W[m,k]*x[b,k,n] + bias[m], M = CQ = 128.
// Epilogue writes split-bf16 (hi + lo) TRANSPOSED to [b][pos n][chan m].
// ---------------------------------------------------------------------------
__global__ __launch_bounds__(256)
void qkconv_kernel(const float* __restrict__ W, const float* __restrict__ bias,
                   const float* __restrict__ x,
                   __nv_bfloat16* __restrict__ hi, __nv_bfloat16* __restrict__ lo)
{
    const int b  = blockIdx.z;
    const int n0 = blockIdx.x * 128;   // position tile; M tile is the full 128

    __shared__ float As[8][128];   // As[k][m]
    __shared__ float Bs[8][128];   // Bs[k][n]

    const int tid = threadIdx.x;
    const int tx = tid % 16, ty = tid / 16;

    const float* xb = x + (size_t)b * Cc * Ll;

    const int aRow = tid >> 1;          // 0..127 (m)
    const int aCol = (tid & 1) * 4;     // 0 / 4  (k)
    const int bRow = tid >> 5;          // 0..7   (k)
    const int bCol = (tid & 31) * 4;    // 0..124 (n)

    float acc[8][8];
    #pragma unroll
    for (int i = 0; i < 8; i++)
        #pragma unroll
        for (int j = 0; j < 8; j++) acc[i][j] = 0.0f;

    for (int k0 = 0; k0 < Cc; k0 += 8) {
        float4 a = *(const float4*)&W[(size_t)aRow * Cc + k0 + aCol];
        As[aCol + 0][aRow] = a.x;
        As[aCol + 1][aRow] = a.y;
        As[aCol + 2][aRow] = a.z;
        As[aCol + 3][aRow] = a.w;
        *(float4*)&Bs[bRow][bCol] =
            *(const float4*)&xb[(size_t)(k0 + bRow) * Ll + n0 + bCol];
        __syncthreads();

        #pragma unroll
        for (int k = 0; k < 8; k++) {
            float rm[8], rn[8];
            #pragma unroll
            for (int i = 0; i < 8; i++) rm[i] = As[k][ty * 8 + i];
            #pragma unroll
            for (int j = 0; j < 8; j++) rn[j] = Bs[k][tx * 8 + j];
            #pragma unroll
            for (int i = 0; i < 8; i++)
                #pragma unroll
                for (int j = 0; j < 8; j++)
                    acc[i][j] = fmaf(rm[i], rn[j], acc[i][j]);
        }
        __syncthreads();
    }

    // Epilogue: split each value into bf16 hi + lo, write [pos][chan].
    __nv_bfloat16* hb = hi + (size_t)b * Ll * CQq;
    __nv_bfloat16* lb = lo + (size_t)b * Ll * CQq;
    #pragma unroll
    for (int j = 0; j < 8; j++) {
        const int n = n0 + tx * 8 + j;
        __nv_bfloat16 vhi[8], vlo[8];
        #pragma unroll
        for (int i = 0; i < 8; i++) {
            const int m = ty * 8 + i;
            float val = acc[i][j] + bias[m];
            __nv_bfloat16 h = __float2bfloat16_rn(val);
            vhi[i] = h;
            vlo[i] = __float2bfloat16_rn(val - __bfloat162float(h));
        }
        *(uint4*)&hb[(size_t)n * CQq + ty * 8] = *(uint4*)vhi;
        *(uint4*)&lb[(size_t)n * CQq + ty * 8] = *(uint4*)vlo;
    }
}

// ---------------------------------------------------------------------------
// energy[b,i,j] = sum_d q[b,d,i]*k[b,d,j] via mma.sync bf16 split:
//   E = qhi*khi + qhi*klo + qlo*khi  (lo*lo dropped, ~2^-16 relative)
// Block: 128x128 E tile, 8 warps (2m x 4n), warp tile 64x32, m16n8k16.
// Operands in smem as [pos][d] bf16, pad 136 -> conflict-free 32-bit frag LDS.
// ---------------------------------------------------------------------------
#define EPAD 136

__device__ __forceinline__ void load_tile_bf16(
    __nv_bfloat16* __restrict__ S, const __nv_bfloat16* __restrict__ src,
    int r0, int tid)
{
    #pragma unroll
    for (int it = 0; it < 8; it++) {
        int idx = it * 256 + tid;
        int r = idx >> 4;            // 0..127
        int c = (idx & 15) * 8;      // 0..120 step 8 (uint4 = 8 bf16)
        *(uint4*)&S[r * EPAD + c] =
            *(const uint4*)&src[(size_t)(r0 + r) * CQq + c];
    }
}

__global__ __launch_bounds__(256)
void energy_mma_kernel(const __nv_bfloat16* __restrict__ qhi,
                       const __nv_bfloat16* __restrict__ qlo,
                       const __nv_bfloat16* __restrict__ khi,
                       const __nv_bfloat16* __restrict__ klo,
                       float* __restrict__ E)
{
    extern __shared__ __nv_bfloat16 smem[];
    __nv_bfloat16* As = smem;                 // [128][EPAD]
    __nv_bfloat16* Bs = smem + 128 * EPAD;

    const int b  = blockIdx.z;
    const int i0 = blockIdx.y * 128;
    const int j0 = blockIdx.x * 128;

    const int tid  = threadIdx.x;
    const int lane = tid & 31;
    const int wid  = tid >> 5;
    const int wm   = wid >> 2;       // 0..1
    const int wn   = wid & 3;        // 0..3
    const int g    = lane >> 2;      // 0..7
    const int t    = lane & 3;       // 0..3

    const size_t boff = (size_t)b * Ll * CQq;
    const __nv_bfloat16* Aptr[3] = {qhi + boff, qhi + boff, qlo + boff};
    const __nv_bfloat16* Bptr[3] = {khi + boff, klo + boff, khi + boff};

    float acc[4][4][4];
    #pragma unroll
    for (int am = 0; am < 4; am++)
        #pragma unroll
        for (int bn = 0; bn < 4; bn++)
            #pragma unroll
            for (int c = 0; c < 4; c++) acc[am][bn][c] = 0.0f;

    #pragma unroll
    for (int p = 0; p < 3; p++) {
        if (p > 0) __syncthreads();
        if (p != 1) load_tile_bf16(As, Aptr[p], i0, tid);  // A unchanged hi->hi
        load_tile_bf16(Bs, Bptr[p], j0, tid);
        __syncthreads();

        #pragma unroll
        for (int ks = 0; ks < 8; ks++) {
            const int k0 = ks * 16;
            uint32_t af[4][4], bf[4][2];
            #pragma unroll
            for (int am = 0; am < 4; am++) {
                const int r = wm * 64 + am * 16 + g;
                af[am][0] = *(const uint32_t*)&As[(r    ) * EPAD + k0 + 2 * t    ];
                af[am][1] = *(const uint32_t*)&As[(r + 8) * EPAD + k0 + 2 * t    ];
                af[am][2] = *(const uint32_t*)&As[(r    ) * EPAD + k0 + 2 * t + 8];
                af[am][3] = *(const uint32_t*)&As[(r + 8) * EPAD + k0 + 2 * t + 8];
            }
            #pragma unroll
            for (int bn = 0; bn < 4; bn++) {
                const int r = wn * 32 + bn * 8 + g;
                bf[bn][0] = *(const uint32_t*)&Bs[r * EPAD + k0 + 2 * t    ];
                bf[bn][1] = *(const uint32_t*)&Bs[r * EPAD + k0 + 2 * t + 8];
            }
            #pragma unroll
            for (int am = 0; am < 4; am++)
                #pragma unroll
                for (int bn = 0; bn < 4; bn++) {
                    asm volatile(
                        "mma.sync.aligned.m16n8k16.row.col.f32.bf16.bf16.f32 "
                        "{%0,%1,%2,%3}, {%4,%5,%6,%7}, {%8,%9}, {%0,%1,%2,%3};\n"
                        : "+f"(acc[am][bn][0]), "+f"(acc[am][bn][1]),
                          "+f"(acc[am][bn][2]), "+f"(acc[am][bn][3])
                        : "r"(af[am][0]), "r"(af[am][1]),
                          "r"(af[am][2]), "r"(af[am][3]),
                          "r"(bf[bn][0]), "r"(bf[bn][1]));
                }
        }
    }

    float* eb = E + (size_t)b * Ll * Ll;
    #pragma unroll
    for (int am = 0; am < 4; am++) {
        const int row = i0 + wm * 64 + am * 16 + g;
        #pragma unroll
        for (int bn = 0; bn < 4; bn++) {
            const int col = j0 + wn * 32 + bn * 8 + 2 * t;
            *(float2*)&eb[(size_t)row * Ll + col] =
                make_float2(acc[am][bn][0], acc[am][bn][1]);
            *(float2*)&eb[(size_t)(row + 8) * Ll + col] =
                make_float2(acc[am][bn][2], acc[am][bn][3]);
        }
    }
}

// ---------------------------------------------------------------------------
// In-place row softmax, float4 loads + warp-shuffle reductions.
// One block (256 thr) per row of 2048.
// ---------------------------------------------------------------------------
__global__ __launch_bounds__(256)
void softmax_kernel(float* __restrict__ att)
{
    const size_t row = blockIdx.x;
    float4* p = (float4*)(att + row * (size_t)Ll);
    const int tid = threadIdx.x;
    const int lane = tid & 31, wrp = tid >> 5;

    float4 v0 = p[tid];
    float4 v1 = p[tid + 256];

    float m = fmaxf(fmaxf(fmaxf(v0.x, v0.y), fmaxf(v0.z, v0.w)),
                    fmaxf(fmaxf(v1.x, v1.y), fmaxf(v1.z, v1.w)));
    #pragma unroll
    for (int s = 16; s > 0; s >>= 1)
        m = fmaxf(m, __shfl_xor_sync(0xffffffffu, m, s));

    __shared__ float red[8];
    if (lane == 0) red[wrp] = m;
    __syncthreads();
    float bm = red[lane & 7];
    #pragma unroll
    for (int s = 4; s > 0; s >>= 1)
        bm = fmaxf(bm, __shfl_xor_sync(0xffffffffu, bm, s));
    m = __shfl_sync(0xffffffffu, bm, 0);

    v0.x = __expf(v0.x - m); v0.y = __expf(v0.y - m);
    v0.z = __expf(v0.z - m); v0.w = __expf(v0.w - m);
    v1.x = __expf(v1.x - m); v1.y = __expf(v1.y - m);
    v1.z = __expf(v1.z - m); v1.w = __expf(v1.w - m);

    float sum = v0.x + v0.y + v0.z + v0.w + v1.x + v1.y + v1.z + v1.w;
    #pragma unroll
    for (int s = 16; s > 0; s >>= 1)
        sum += __shfl_xor_sync(0xffffffffu, sum, s);
    __syncthreads();
    if (lane == 0) red[wrp] = sum;
    __syncthreads();
    float bs = red[lane & 7];
    #pragma unroll
    for (int s = 4; s > 0; s >>= 1)
        bs += __shfl_xor_sync(0xffffffffu, bs, s);
    const float inv = 1.0f / __shfl_sync(0xffffffffu, bs, 0);

    v0.x *= inv; v0.y *= inv; v0.z *= inv; v0.w *= inv;
    v1.x *= inv; v1.y *= inv; v1.z *= inv; v1.w *= inv;
    p[tid]       = v0;
    p[tid + 256] = v1;
}

// ---------------------------------------------------------------------------
// gamma == 0 fast path: out = x. Gated on gamma[0]==0.
// ---------------------------------------------------------------------------
__global__ __launch_bounds__(256)
void copy_x_kernel(const float* __restrict__ x, float* __restrict__ out,
                   const float* __restrict__ gamma)
{
    if (gamma[0] != 0.0f) return;
    const size_t idx = ((size_t)blockIdx.x * 256 + threadIdx.x) * 4;
    *(float4*)&out[idx] = *(const float4*)&x[idx];
}

// ---------------------------------------------------------------------------
// gamma != 0 path kernels (gated; full-precision fallback).
// ---------------------------------------------------------------------------
__global__ __launch_bounds__(256)
void vconv_kernel(const float* __restrict__ W, const float* __restrict__ bias,
                  const float* __restrict__ x, float* __restrict__ out,
                  const float* __restrict__ gamma)
{
    if (gamma[0] == 0.0f) return;
    const int b  = blockIdx.z;
    const int m0 = blockIdx.y * 128;
    const int n0 = blockIdx.x * 128;

    __shared__ float As[8][128];
    __shared__ float Bs[8][128];

    const int tid = threadIdx.x;
    const int tx = tid % 16, ty = tid / 16;
    const float* xb = x + (size_t)b * Cc * Ll;

    const int aRow = tid >> 1;
    const int aCol = (tid & 1) * 4;
    const int bRow = tid >> 5;
    const int bCol = (tid & 31) * 4;

    float acc[8][8];
    #pragma unroll
    for (int i = 0; i < 8; i++)
        #pragma unroll
        for (int j = 0; j < 8; j++) acc[i][j] = 0.0f;

    for (int k0 = 0; k0 < Cc; k0 += 8) {
        float4 a = *(const float4*)&W[(size_t)(m0 + aRow) * Cc + k0 + aCol];
        As[aCol + 0][aRow] = a.x;
        As[aCol + 1][aRow] = a.y;
        As[aCol + 2][aRow] = a.z;
        As[aCol + 3][aRow] = a.w;
        *(float4*)&Bs[bRow][bCol] =
            *(const float4*)&xb[(size_t)(k0 + bRow) * Ll + n0 + bCol];
        __syncthreads();

        #pragma unroll
        for (int k = 0; k < 8; k++) {
            float rm[8], rn[8];
            #pragma unroll
            for (int i = 0; i < 8; i++) rm[i] = As[k][ty * 8 + i];
            #pragma unroll
            for (int j = 0; j < 8; j++) rn[j] = Bs[k][tx * 8 + j];
            #pragma unroll
            for (int i = 0; i < 8; i++)
                #pragma unroll
                for (int j = 0; j < 8; j++)
                    acc[i][j] = fmaf(rm[i], rn[j], acc[i][j]);
        }
        __syncthreads();
    }

    float* ob = out + (size_t)b * Cc * Ll;
    #pragma unroll
    for (int i = 0; i < 8; i++) {
        const int m = m0 + ty * 8 + i;
        const float bb = bias[m];
        float* po = ob + (size_t)m * Ll + n0 + tx * 8;
        *(float4*)po = make_float4(acc[i][0] + bb, acc[i][1] + bb,
                                   acc[i][2] + bb, acc[i][3] + bb);
        *(float4*)(po + 4) = make_float4(acc[i][4] + bb, acc[i][5] + bb,
                                         acc[i][6] + bb, acc[i][7] + bb);
    }
}

__global__ __launch_bounds__(256)
void outgemm_kernel(const float* __restrict__ att, const float* __restrict__ x,
                    float* __restrict__ out, const float* __restrict__ gamma)
{
    const float g = gamma[0];
    if (g == 0.0f) return;
    const int b  = blockIdx.z;
    const int c0 = blockIdx.y * 128;
    const int i0 = blockIdx.x * 128;

    __shared__ float Vs[8][128];
    __shared__ float Ts[8][128];

    const int tid = threadIdx.x;
    const int tx = tid % 16, ty = tid / 16;
    const int aRow = tid >> 1;
    const int aCol = (tid & 1) * 4;

    const float* vb = g_v + (size_t)b * Cc * Ll;
    const float* ab = att + (size_t)b * Ll * Ll;

    float acc[8][8];
    #pragma unroll
    for (int i = 0; i < 8; i++)
        #pragma unroll
        for (int j = 0; j < 8; j++) acc[i][j] = 0.0f;

    for (int j0 = 0; j0 < Ll; j0 += 8) {
        float4 a = *(const float4*)&vb[(size_t)(c0 + aRow) * Ll + j0 + aCol];
        Vs[aCol + 0][aRow] = a.x;
        Vs[aCol + 1][aRow] = a.y;
        Vs[aCol + 2][aRow] = a.z;
        Vs[aCol + 3][aRow] = a.w;
        float4 tt = *(const float4*)&ab[(size_t)(i0 + aRow) * Ll + j0 + aCol];
        Ts[aCol + 0][aRow] = tt.x;
        Ts[aCol + 1][aRow] = tt.y;
        Ts[aCol + 2][aRow] = tt.z;
        Ts[aCol + 3][aRow] = tt.w;
        __syncthreads();

        #pragma unroll
        for (int k = 0; k < 8; k++) {
            float rm[8], rn[8];
            #pragma unroll
            for (int i = 0; i < 8; i++) rm[i] = Vs[k][ty * 8 + i];
            #pragma unroll
            for (int j = 0; j < 8; j++) rn[j] = Ts[k][tx * 8 + j];
            #pragma unroll
            for (int i = 0; i < 8; i++)
                #pragma unroll
                for (int j = 0; j < 8; j++)
                    acc[i][j] = fmaf(rm[i], rn[j], acc[i][j]);
        }
        __syncthreads();
    }

    #pragma unroll
    for (int i = 0; i < 8; i++) {
        const size_t off = (size_t)b * Cc * Ll + (size_t)(c0 + ty * 8 + i) * Ll
                         + i0 + tx * 8;
        #pragma unroll
        for (int j = 0; j < 8; j++)
            out[off + j] = g * acc[i][j] + x[off + j];
    }
}

// ---------------------------------------------------------------------------
extern "C" void kernel_launch(void* const* d_in, const int* in_sizes, int n_in,
                              void* d_out, int out_size)
{
    (void)in_sizes; (void)n_in;
    const float* x     = (const float*)d_in[0];
    const float* q_w   = (const float*)d_in[1];
    const float* q_b   = (const float*)d_in[2];
    const float* k_w   = (const float*)d_in[3];
    const float* k_b   = (const float*)d_in[4];
    const float* v_w   = (const float*)d_in[5];
    const float* v_b   = (const float*)d_in[6];
    const float* gamma = (const float*)d_in[7];

    const size_t BCL = (size_t)Bb * Cc * Ll;        // 8388608
    const size_t BLL = (size_t)Bb * Ll * Ll;        // 33554432

    float* out_ptr;
    float* att_ptr;
    if ((size_t)out_size >= BCL + BLL) {
        out_ptr = (float*)d_out;
        att_ptr = (float*)d_out + BCL;
    } else if ((size_t)out_size == BLL) {
        cudaGetSymbolAddress((void**)&out_ptr, g_outbuf);
        att_ptr = (float*)d_out;
    } else {
        out_ptr = (float*)d_out;
        cudaGetSymbolAddress((void**)&att_ptr, g_att);
    }
    __nv_bfloat16 *qhi, *qlo, *khi, *klo;
    cudaGetSymbolAddress((void**)&qhi, g_qhi);
    cudaGetSymbolAddress((void**)&qlo, g_qlo);
    cudaGetSymbolAddress((void**)&khi, g_khi);
    cudaGetSymbolAddress((void**)&klo, g_klo);
    float* vbuf; cudaGetSymbolAddress((void**)&vbuf, g_v);

    static int smem_set = 0;
    const int ENERGY_SMEM = 2 * 128 * EPAD * (int)sizeof(__nv_bfloat16); // 69632
    if (!smem_set) {
        cudaFuncSetAttribute(energy_mma_kernel,
                             cudaFuncAttributeMaxDynamicSharedMemorySize,
                             ENERGY_SMEM);
        smem_set = 1;
    }

    dim3 blk(256);

    // q and k projections -> split bf16, [pos][d] layout
    qkconv_kernel<<<dim3(Ll / 128, 1, Bb), blk>>>(q_w, q_b, x, qhi, qlo);
    qkconv_kernel<<<dim3(Ll / 128, 1, Bb), blk>>>(k_w, k_b, x, khi, klo);

    // energy on tensor cores -> attention region, softmax in place
    energy_mma_kernel<<<dim3(Ll / 128, Ll / 128, Bb), blk, ENERGY_SMEM>>>(
        qhi, qlo, khi, klo, att_ptr);
    softmax_kernel<<<dim3(Bb * Ll), blk>>>(att_ptr);

    // out path: gamma==0 -> copy; gamma!=0 -> v conv + out GEMM
    copy_x_kernel<<<dim3((unsigned)(BCL / (256 * 4))), blk>>>(x, out_ptr, gamma);
    vconv_kernel<<<dim3(Ll / 128, Cc / 128, Bb), blk>>>(v_w, v_b, x, vbuf, gamma);
    outgemm_kernel<<<dim3(Ll / 128, Cc / 128, Bb), blk>>>(att_ptr, x, out_ptr, gamma);
}

// round 9
// speedup vs baseline: 2.0320x; 1.5385x over previous
#include <cuda_runtime.h>
#include <cuda_bf16.h>
#include <stdint.h>
#include <math.h>

#define Bb 8
#define Cc 512
#define Ll 2048
#define CQq 128

// Static device scratch (allocation-free rule: __device__ globals).
__device__ __nv_bfloat16 g_xhi[(size_t)Bb * Ll * Cc];    // x^T split hi [b][pos][c]
__device__ __nv_bfloat16 g_xlo[(size_t)Bb * Ll * Cc];
__device__ __nv_bfloat16 g_wqhi[CQq * Cc];
__device__ __nv_bfloat16 g_wqlo[CQq * Cc];
__device__ __nv_bfloat16 g_wkhi[CQq * Cc];
__device__ __nv_bfloat16 g_wklo[CQq * Cc];
__device__ __nv_bfloat16 g_qhi[(size_t)Bb * Ll * CQq];   // [b][pos][d]
__device__ __nv_bfloat16 g_qlo[(size_t)Bb * Ll * CQq];
__device__ __nv_bfloat16 g_khi[(size_t)Bb * Ll * CQq];
__device__ __nv_bfloat16 g_klo[(size_t)Bb * Ll * CQq];
__device__ float g_v[(size_t)Bb * Cc * Ll];              // gamma!=0 path only
__device__ float g_att[(size_t)Bb * Ll * Ll];            // fallback
__device__ float g_outbuf[(size_t)Bb * Cc * Ll];         // fallback

// smem tile pitch for 64-wide bf16 chunks: 72 -> word stride 36 -> banks (4g+t) distinct
#define CPAD 72
#define TILE_HW (128 * CPAD)   // bf16 elements per tile

// ---------------------------------------------------------------------------
// Split W (CQ x C fp32) into bf16 hi/lo. grid (128, 2), block 128.
// ---------------------------------------------------------------------------
__global__ __launch_bounds__(128)
void wsplit_kernel(const float* __restrict__ q_w, const float* __restrict__ k_w)
{
    const int row = blockIdx.x;
    const int s   = blockIdx.y;
    const float* W = s ? k_w : q_w;
    __nv_bfloat16* ho = s ? g_wkhi : g_wqhi;
    __nv_bfloat16* lo = s ? g_wklo : g_wqlo;

    const int c = threadIdx.x * 4;
    float4 v = *(const float4*)&W[(size_t)row * Cc + c];
    __nv_bfloat16 h[4], l[4];
    float vv[4] = {v.x, v.y, v.z, v.w};
    #pragma unroll
    for (int i = 0; i < 4; i++) {
        h[i] = __float2bfloat16_rn(vv[i]);
        l[i] = __float2bfloat16_rn(vv[i] - __bfloat162float(h[i]));
    }
    *(uint2*)&ho[(size_t)row * Cc + c] = *(uint2*)h;
    *(uint2*)&lo[(size_t)row * Cc + c] = *(uint2*)l;
}

// ---------------------------------------------------------------------------
// Transpose + split x: [b][c][l] fp32 -> [b][l][c] bf16 hi/lo.
// Tile 64(c) x 64(l), grid (L/64, C/64, B), block 256.
// ---------------------------------------------------------------------------
__global__ __launch_bounds__(256)
void xsplit_kernel(const float* __restrict__ x)
{
    __shared__ float ts[64][65];
    const int b  = blockIdx.z;
    const int l0 = blockIdx.x * 64;
    const int c0 = blockIdx.y * 64;
    const int tid = threadIdx.x;

    const float* xb = x + (size_t)b * Cc * Ll;
    const int ly = tid >> 4;          // 0..15
    const int lx = (tid & 15) * 4;    // 0..60
    #pragma unroll
    for (int rr = 0; rr < 4; rr++) {
        const int cl = ly + rr * 16;
        float4 v = *(const float4*)&xb[(size_t)(c0 + cl) * Ll + l0 + lx];
        ts[cl][lx + 0] = v.x;
        ts[cl][lx + 1] = v.y;
        ts[cl][lx + 2] = v.z;
        ts[cl][lx + 3] = v.w;
    }
    __syncthreads();

    __nv_bfloat16* xh = g_xhi + (size_t)b * Ll * Cc;
    __nv_bfloat16* xl = g_xlo + (size_t)b * Ll * Cc;
    const int wy = tid >> 3;          // 0..31
    const int wx = (tid & 7) * 8;     // 0..56
    #pragma unroll
    for (int rr = 0; rr < 2; rr++) {
        const int ll = wy + rr * 32;
        __nv_bfloat16 h[8], l[8];
        #pragma unroll
        for (int e = 0; e < 8; e++) {
            float v = ts[wx + e][ll];
            h[e] = __float2bfloat16_rn(v);
            l[e] = __float2bfloat16_rn(v - __bfloat162float(h[e]));
        }
        *(uint4*)&xh[(size_t)(l0 + ll) * Cc + c0 + wx] = *(uint4*)h;
        *(uint4*)&xl[(size_t)(l0 + ll) * Cc + c0 + wx] = *(uint4*)l;
    }
}

// ---------------------------------------------------------------------------
// mma helper
// ---------------------------------------------------------------------------
__device__ __forceinline__ void mma16816(float* acc, const uint32_t* a,
                                         const uint32_t* bfr)
{
    asm volatile(
        "mma.sync.aligned.m16n8k16.row.col.f32.bf16.bf16.f32 "
        "{%0,%1,%2,%3}, {%4,%5,%6,%7}, {%8,%9}, {%0,%1,%2,%3};\n"
        : "+f"(acc[0]), "+f"(acc[1]), "+f"(acc[2]), "+f"(acc[3])
        : "r"(a[0]), "r"(a[1]), "r"(a[2]), "r"(a[3]),
          "r"(bfr[0]), "r"(bfr[1]));
}

// ---------------------------------------------------------------------------
// q/k conv on tensor cores, split-bf16 3-combo:
//   out[pos][d] = sum_c xT[pos][c] * W[d][c] + bias[d]
// grid (L/128, 2 {q,k}, B), block 256 (8 warps, 2m x 4n), K=512 in 8 chunks.
// Output written as split bf16 hi/lo in [pos][d].
// ---------------------------------------------------------------------------
__global__ __launch_bounds__(256)
void qkconv_mma_kernel(const float* __restrict__ q_b, const float* __restrict__ k_b)
{
    extern __shared__ __nv_bfloat16 sm[];
    __nv_bfloat16* Ahi = sm;
    __nv_bfloat16* Alo = sm + TILE_HW;
    __nv_bfloat16* Bhi = sm + 2 * TILE_HW;
    __nv_bfloat16* Blo = sm + 3 * TILE_HW;
    __shared__ float sbias[128];

    const int p0 = blockIdx.x * 128;
    const int s  = blockIdx.y;
    const int b  = blockIdx.z;

    const __nv_bfloat16* whi = s ? g_wkhi : g_wqhi;
    const __nv_bfloat16* wlo = s ? g_wklo : g_wqlo;
    const float* bias = s ? k_b : q_b;

    const int tid  = threadIdx.x;
    const int lane = tid & 31;
    const int wid  = tid >> 5;
    const int wm   = wid >> 2;
    const int wn   = wid & 3;
    const int g    = lane >> 2;
    const int t    = lane & 3;

    if (tid < 128) sbias[tid] = bias[tid];

    const __nv_bfloat16* xh = g_xhi + (size_t)b * Ll * Cc;
    const __nv_bfloat16* xl = g_xlo + (size_t)b * Ll * Cc;

    float acc[4][4][4];
    #pragma unroll
    for (int am = 0; am < 4; am++)
        #pragma unroll
        for (int bn = 0; bn < 4; bn++)
            #pragma unroll
            for (int c = 0; c < 4; c++) acc[am][bn][c] = 0.0f;

    for (int it = 0; it < 8; it++) {
        const int c0 = it * 64;
        if (it) __syncthreads();
        #pragma unroll
        for (int q = 0; q < 4; q++) {
            const int idx = q * 256 + tid;
            const int r  = idx >> 3;
            const int cc = (idx & 7) * 8;
            *(uint4*)&Ahi[r * CPAD + cc] = *(const uint4*)&xh[(size_t)(p0 + r) * Cc + c0 + cc];
            *(uint4*)&Alo[r * CPAD + cc] = *(const uint4*)&xl[(size_t)(p0 + r) * Cc + c0 + cc];
            *(uint4*)&Bhi[r * CPAD + cc] = *(const uint4*)&whi[(size_t)r * Cc + c0 + cc];
            *(uint4*)&Blo[r * CPAD + cc] = *(const uint4*)&wlo[(size_t)r * Cc + c0 + cc];
        }
        __syncthreads();

        #pragma unroll
        for (int ks = 0; ks < 4; ks++) {
            const int k0 = ks * 16;
            uint32_t bh[4][2], bl[4][2];
            #pragma unroll
            for (int bn = 0; bn < 4; bn++) {
                const int r = wn * 32 + bn * 8 + g;
                bh[bn][0] = *(const uint32_t*)&Bhi[r * CPAD + k0 + 2 * t    ];
                bh[bn][1] = *(const uint32_t*)&Bhi[r * CPAD + k0 + 2 * t + 8];
                bl[bn][0] = *(const uint32_t*)&Blo[r * CPAD + k0 + 2 * t    ];
                bl[bn][1] = *(const uint32_t*)&Blo[r * CPAD + k0 + 2 * t + 8];
            }
            #pragma unroll
            for (int am = 0; am < 4; am++) {
                const int r = wm * 64 + am * 16 + g;
                uint32_t ah[4], al[4];
                ah[0] = *(const uint32_t*)&Ahi[(r    ) * CPAD + k0 + 2 * t    ];
                ah[1] = *(const uint32_t*)&Ahi[(r + 8) * CPAD + k0 + 2 * t    ];
                ah[2] = *(const uint32_t*)&Ahi[(r    ) * CPAD + k0 + 2 * t + 8];
                ah[3] = *(const uint32_t*)&Ahi[(r + 8) * CPAD + k0 + 2 * t + 8];
                al[0] = *(const uint32_t*)&Alo[(r    ) * CPAD + k0 + 2 * t    ];
                al[1] = *(const uint32_t*)&Alo[(r + 8) * CPAD + k0 + 2 * t    ];
                al[2] = *(const uint32_t*)&Alo[(r    ) * CPAD + k0 + 2 * t + 8];
                al[3] = *(const uint32_t*)&Alo[(r + 8) * CPAD + k0 + 2 * t + 8];
                #pragma unroll
                for (int bn = 0; bn < 4; bn++) {
                    mma16816(acc[am][bn], ah, bh[bn]);
                    mma16816(acc[am][bn], ah, bl[bn]);
                    mma16816(acc[am][bn], al, bh[bn]);
                }
            }
        }
    }

    __nv_bfloat16* hb = (s ? g_khi : g_qhi) + (size_t)b * Ll * CQq;
    __nv_bfloat16* lb = (s ? g_klo : g_qlo) + (size_t)b * Ll * CQq;
    #pragma unroll
    for (int am = 0; am < 4; am++) {
        const int r0 = wm * 64 + am * 16 + g;
        #pragma unroll
        for (int bn = 0; bn < 4; bn++) {
            const int col = wn * 32 + bn * 8 + 2 * t;
            const float b0 = sbias[col], b1 = sbias[col + 1];
            #pragma unroll
            for (int half = 0; half < 2; half++) {
                const int row = r0 + half * 8;
                const float v0 = acc[am][bn][half * 2 + 0] + b0;
                const float v1 = acc[am][bn][half * 2 + 1] + b1;
                __nv_bfloat16 h0 = __float2bfloat16_rn(v0);
                __nv_bfloat16 h1 = __float2bfloat16_rn(v1);
                __nv_bfloat16 l0 = __float2bfloat16_rn(v0 - __bfloat162float(h0));
                __nv_bfloat16 l1 = __float2bfloat16_rn(v1 - __bfloat162float(h1));
                *(__nv_bfloat162*)&hb[(size_t)(p0 + row) * CQq + col] =
                    __halves2bfloat162(h0, h1);
                *(__nv_bfloat162*)&lb[(size_t)(p0 + row) * CQq + col] =
                    __halves2bfloat162(l0, l1);
            }
        }
    }
}

// ---------------------------------------------------------------------------
// energy[b,i,j] = sum_d q[b,i,d]*k[b,j,d], split-bf16 3-combo, single smem
// residency (hi+lo tiles together). K=128 in 2 chunks of 64.
// ---------------------------------------------------------------------------
__global__ __launch_bounds__(256)
void energy_mma_kernel(float* __restrict__ E)
{
    extern __shared__ __nv_bfloat16 sm[];
    __nv_bfloat16* Ahi = sm;
    __nv_bfloat16* Alo = sm + TILE_HW;
    __nv_bfloat16* Bhi = sm + 2 * TILE_HW;
    __nv_bfloat16* Blo = sm + 3 * TILE_HW;

    const int b  = blockIdx.z;
    const int i0 = blockIdx.y * 128;
    const int j0 = blockIdx.x * 128;

    const int tid  = threadIdx.x;
    const int lane = tid & 31;
    const int wid  = tid >> 5;
    const int wm   = wid >> 2;
    const int wn   = wid & 3;
    const int g    = lane >> 2;
    const int t    = lane & 3;

    const size_t boff = (size_t)b * Ll * CQq;
    const __nv_bfloat16* qh = g_qhi + boff;
    const __nv_bfloat16* ql = g_qlo + boff;
    const __nv_bfloat16* kh = g_khi + boff;
    const __nv_bfloat16* kl = g_klo + boff;

    float acc[4][4][4];
    #pragma unroll
    for (int am = 0; am < 4; am++)
        #pragma unroll
        for (int bn = 0; bn < 4; bn++)
            #pragma unroll
            for (int c = 0; c < 4; c++) acc[am][bn][c] = 0.0f;

    #pragma unroll
    for (int it = 0; it < 2; it++) {
        const int c0 = it * 64;
        if (it) __syncthreads();
        #pragma unroll
        for (int q = 0; q < 4; q++) {
            const int idx = q * 256 + tid;
            const int r  = idx >> 3;
            const int cc = (idx & 7) * 8;
            *(uint4*)&Ahi[r * CPAD + cc] = *(const uint4*)&qh[(size_t)(i0 + r) * CQq + c0 + cc];
            *(uint4*)&Alo[r * CPAD + cc] = *(const uint4*)&ql[(size_t)(i0 + r) * CQq + c0 + cc];
            *(uint4*)&Bhi[r * CPAD + cc] = *(const uint4*)&kh[(size_t)(j0 + r) * CQq + c0 + cc];
            *(uint4*)&Blo[r * CPAD + cc] = *(const uint4*)&kl[(size_t)(j0 + r) * CQq + c0 + cc];
        }
        __syncthreads();

        #pragma unroll
        for (int ks = 0; ks < 4; ks++) {
            const int k0 = ks * 16;
            uint32_t bh[4][2], bl[4][2];
            #pragma unroll
            for (int bn = 0; bn < 4; bn++) {
                const int r = wn * 32 + bn * 8 + g;
                bh[bn][0] = *(const uint32_t*)&Bhi[r * CPAD + k0 + 2 * t    ];
                bh[bn][1] = *(const uint32_t*)&Bhi[r * CPAD + k0 + 2 * t + 8];
                bl[bn][0] = *(const uint32_t*)&Blo[r * CPAD + k0 + 2 * t    ];
                bl[bn][1] = *(const uint32_t*)&Blo[r * CPAD + k0 + 2 * t + 8];
            }
            #pragma unroll
            for (int am = 0; am < 4; am++) {
                const int r = wm * 64 + am * 16 + g;
                uint32_t ah[4], al[4];
                ah[0] = *(const uint32_t*)&Ahi[(r    ) * CPAD + k0 + 2 * t    ];
                ah[1] = *(const uint32_t*)&Ahi[(r + 8) * CPAD + k0 + 2 * t    ];
                ah[2] = *(const uint32_t*)&Ahi[(r    ) * CPAD + k0 + 2 * t + 8];
                ah[3] = *(const uint32_t*)&Ahi[(r + 8) * CPAD + k0 + 2 * t + 8];
                al[0] = *(const uint32_t*)&Alo[(r    ) * CPAD + k0 + 2 * t    ];
                al[1] = *(const uint32_t*)&Alo[(r + 8) * CPAD + k0 + 2 * t    ];
                al[2] = *(const uint32_t*)&Alo[(r    ) * CPAD + k0 + 2 * t + 8];
                al[3] = *(const uint32_t*)&Alo[(r + 8) * CPAD + k0 + 2 * t + 8];
                #pragma unroll
                for (int bn = 0; bn < 4; bn++) {
                    mma16816(acc[am][bn], ah, bh[bn]);
                    mma16816(acc[am][bn], ah, bl[bn]);
                    mma16816(acc[am][bn], al, bh[bn]);
                }
            }
        }
    }

    float* eb = E + (size_t)b * Ll * Ll;
    #pragma unroll
    for (int am = 0; am < 4; am++) {
        const int row = i0 + wm * 64 + am * 16 + g;
        #pragma unroll
        for (int bn = 0; bn < 4; bn++) {
            const int col = j0 + wn * 32 + bn * 8 + 2 * t;
            *(float2*)&eb[(size_t)row * Ll + col] =
                make_float2(acc[am][bn][0], acc[am][bn][1]);
            *(float2*)&eb[(size_t)(row + 8) * Ll + col] =
                make_float2(acc[am][bn][2], acc[am][bn][3]);
        }
    }
}

// ---------------------------------------------------------------------------
// In-place row softmax, float4 loads + warp-shuffle reductions.
// ---------------------------------------------------------------------------
__global__ __launch_bounds__(256)
void softmax_kernel(float* __restrict__ att)
{
    const size_t row = blockIdx.x;
    float4* p = (float4*)(att + row * (size_t)Ll);
    const int tid = threadIdx.x;
    const int lane = tid & 31, wrp = tid >> 5;

    float4 v0 = p[tid];
    float4 v1 = p[tid + 256];

    float m = fmaxf(fmaxf(fmaxf(v0.x, v0.y), fmaxf(v0.z, v0.w)),
                    fmaxf(fmaxf(v1.x, v1.y), fmaxf(v1.z, v1.w)));
    #pragma unroll
    for (int s = 16; s > 0; s >>= 1)
        m = fmaxf(m, __shfl_xor_sync(0xffffffffu, m, s));

    __shared__ float red[8];
    if (lane == 0) red[wrp] = m;
    __syncthreads();
    float bm = red[lane & 7];
    #pragma unroll
    for (int s = 4; s > 0; s >>= 1)
        bm = fmaxf(bm, __shfl_xor_sync(0xffffffffu, bm, s));
    m = __shfl_sync(0xffffffffu, bm, 0);

    v0.x = __expf(v0.x - m); v0.y = __expf(v0.y - m);
    v0.z = __expf(v0.z - m); v0.w = __expf(v0.w - m);
    v1.x = __expf(v1.x - m); v1.y = __expf(v1.y - m);
    v1.z = __expf(v1.z - m); v1.w = __expf(v1.w - m);

    float sum = v0.x + v0.y + v0.z + v0.w + v1.x + v1.y + v1.z + v1.w;
    #pragma unroll
    for (int s = 16; s > 0; s >>= 1)
        sum += __shfl_xor_sync(0xffffffffu, sum, s);
    __syncthreads();
    if (lane == 0) red[wrp] = sum;
    __syncthreads();
    float bs = red[lane & 7];
    #pragma unroll
    for (int s = 4; s > 0; s >>= 1)
        bs += __shfl_xor_sync(0xffffffffu, bs, s);
    const float inv = 1.0f / __shfl_sync(0xffffffffu, bs, 0);

    v0.x *= inv; v0.y *= inv; v0.z *= inv; v0.w *= inv;
    v1.x *= inv; v1.y *= inv; v1.z *= inv; v1.w *= inv;
    p[tid]       = v0;
    p[tid + 256] = v1;
}

// ---------------------------------------------------------------------------
// gamma == 0 fast path: out = x. Gated on gamma[0]==0.
// ---------------------------------------------------------------------------
__global__ __launch_bounds__(256)
void copy_x_kernel(const float* __restrict__ x, float* __restrict__ out,
                   const float* __restrict__ gamma)
{
    if (gamma[0] != 0.0f) return;
    const size_t idx = ((size_t)blockIdx.x * 256 + threadIdx.x) * 4;
    *(float4*)&out[idx] = *(const float4*)&x[idx];
}

// ---------------------------------------------------------------------------
// gamma != 0 path kernels (gated; full-precision fallback).
// ---------------------------------------------------------------------------
__global__ __launch_bounds__(256)
void vconv_kernel(const float* __restrict__ W, const float* __restrict__ bias,
                  const float* __restrict__ x, float* __restrict__ out,
                  const float* __restrict__ gamma)
{
    if (gamma[0] == 0.0f) return;
    const int b  = blockIdx.z;
    const int m0 = blockIdx.y * 128;
    const int n0 = blockIdx.x * 128;

    __shared__ float As[8][128];
    __shared__ float Bs[8][128];

    const int tid = threadIdx.x;
    const int tx = tid % 16, ty = tid / 16;
    const float* xb = x + (size_t)b * Cc * Ll;

    const int aRow = tid >> 1;
    const int aCol = (tid & 1) * 4;
    const int bRow = tid >> 5;
    const int bCol = (tid & 31) * 4;

    float acc[8][8];
    #pragma unroll
    for (int i = 0; i < 8; i++)
        #pragma unroll
        for (int j = 0; j < 8; j++) acc[i][j] = 0.0f;

    for (int k0 = 0; k0 < Cc; k0 += 8) {
        float4 a = *(const float4*)&W[(size_t)(m0 + aRow) * Cc + k0 + aCol];
        As[aCol + 0][aRow] = a.x;
        As[aCol + 1][aRow] = a.y;
        As[aCol + 2][aRow] = a.z;
        As[aCol + 3][aRow] = a.w;
        *(float4*)&Bs[bRow][bCol] =
            *(const float4*)&xb[(size_t)(k0 + bRow) * Ll + n0 + bCol];
        __syncthreads();

        #pragma unroll
        for (int k = 0; k < 8; k++) {
            float rm[8], rn[8];
            #pragma unroll
            for (int i = 0; i < 8; i++) rm[i] = As[k][ty * 8 + i];
            #pragma unroll
            for (int j = 0; j < 8; j++) rn[j] = Bs[k][tx * 8 + j];
            #pragma unroll
            for (int i = 0; i < 8; i++)
                #pragma unroll
                for (int j = 0; j < 8; j++)
                    acc[i][j] = fmaf(rm[i], rn[j], acc[i][j]);
        }
        __syncthreads();
    }

    float* ob = out + (size_t)b * Cc * Ll;
    #pragma unroll
    for (int i = 0; i < 8; i++) {
        const int m = m0 + ty * 8 + i;
        const float bb = bias[m];
        float* po = ob + (size_t)m * Ll + n0 + tx * 8;
        *(float4*)po = make_float4(acc[i][0] + bb, acc[i][1] + bb,
                                   acc[i][2] + bb, acc[i][3] + bb);
        *(float4*)(po + 4) = make_float4(acc[i][4] + bb, acc[i][5] + bb,
                                         acc[i][6] + bb, acc[i][7] + bb);
    }
}

__global__ __launch_bounds__(256)
void outgemm_kernel(const float* __restrict__ att, const float* __restrict__ x,
                    float* __restrict__ out, const float* __restrict__ gamma)
{
    const float g = gamma[0];
    if (g == 0.0f) return;
    const int b  = blockIdx.z;
    const int c0 = blockIdx.y * 128;
    const int i0 = blockIdx.x * 128;

    __shared__ float Vs[8][128];
    __shared__ float Ts[8][128];

    const int tid = threadIdx.x;
    const int tx = tid % 16, ty = tid / 16;
    const int aRow = tid >> 1;
    const int aCol = (tid & 1) * 4;

    const float* vb = g_v + (size_t)b * Cc * Ll;
    const float* ab = att + (size_t)b * Ll * Ll;

    float acc[8][8];
    #pragma unroll
    for (int i = 0; i < 8; i++)
        #pragma unroll
        for (int j = 0; j < 8; j++) acc[i][j] = 0.0f;

    for (int j0 = 0; j0 < Ll; j0 += 8) {
        float4 a = *(const float4*)&vb[(size_t)(c0 + aRow) * Ll + j0 + aCol];
        Vs[aCol + 0][aRow] = a.x;
        Vs[aCol + 1][aRow] = a.y;
        Vs[aCol + 2][aRow] = a.z;
        Vs[aCol + 3][aRow] = a.w;
        float4 tt = *(const float4*)&ab[(size_t)(i0 + aRow) * Ll + j0 + aCol];
        Ts[aCol + 0][aRow] = tt.x;
        Ts[aCol + 1][aRow] = tt.y;
        Ts[aCol + 2][aRow] = tt.z;
        Ts[aCol + 3][aRow] = tt.w;
        __syncthreads();

        #pragma unroll
        for (int k = 0; k < 8; k++) {
            float rm[8], rn[8];
            #pragma unroll
            for (int i = 0; i < 8; i++) rm[i] = Vs[k][ty * 8 + i];
            #pragma unroll
            for (int j = 0; j < 8; j++) rn[j] = Ts[k][tx * 8 + j];
            #pragma unroll
            for (int i = 0; i < 8; i++)
                #pragma unroll
                for (int j = 0; j < 8; j++)
                    acc[i][j] = fmaf(rm[i], rn[j], acc[i][j]);
        }
        __syncthreads();
    }

    #pragma unroll
    for (int i = 0; i < 8; i++) {
        const size_t off = (size_t)b * Cc * Ll + (size_t)(c0 + ty * 8 + i) * Ll
                         + i0 + tx * 8;
        #pragma unroll
        for (int j = 0; j < 8; j++)
            out[off + j] = g * acc[i][j] + x[off + j];
    }
}

// ---------------------------------------------------------------------------
extern "C" void kernel_launch(void* const* d_in, const int* in_sizes, int n_in,
                              void* d_out, int out_size)
{
    (void)in_sizes; (void)n_in;
    const float* x     = (const float*)d_in[0];
    const float* q_w   = (const float*)d_in[1];
    const float* q_b   = (const float*)d_in[2];
    const float* k_w   = (const float*)d_in[3];
    const float* k_b   = (const float*)d_in[4];
    const float* v_w   = (const float*)d_in[5];
    const float* v_b   = (const float*)d_in[6];
    const float* gamma = (const float*)d_in[7];

    const size_t BCL = (size_t)Bb * Cc * Ll;        // 8388608
    const size_t BLL = (size_t)Bb * Ll * Ll;        // 33554432

    float* out_ptr;
    float* att_ptr;
    if ((size_t)out_size >= BCL + BLL) {
        out_ptr = (float*)d_out;
        att_ptr = (float*)d_out + BCL;
    } else if ((size_t)out_size == BLL) {
        cudaGetSymbolAddress((void**)&out_ptr, g_outbuf);
        att_ptr = (float*)d_out;
    } else {
        out_ptr = (float*)d_out;
        cudaGetSymbolAddress((void**)&att_ptr, g_att);
    }
    float* vbuf; cudaGetSymbolAddress((void**)&vbuf, g_v);

    static int smem_set = 0;
    const int MMA_SMEM = 4 * TILE_HW * (int)sizeof(__nv_bfloat16); // 73728
    if (!smem_set) {
        cudaFuncSetAttribute(energy_mma_kernel,
                             cudaFuncAttributeMaxDynamicSharedMemorySize,
                             MMA_SMEM);
        cudaFuncSetAttribute(qkconv_mma_kernel,
                             cudaFuncAttributeMaxDynamicSharedMemorySize,
                             MMA_SMEM);
        smem_set = 1;
    }

    dim3 blk(256);

    // split inputs for tensor-core path
    wsplit_kernel<<<dim3(CQq, 2), dim3(128)>>>(q_w, k_w);
    xsplit_kernel<<<dim3(Ll / 64, Cc / 64, Bb), blk>>>(x);

    // q and k projections on tensor cores -> split bf16 [pos][d]
    qkconv_mma_kernel<<<dim3(Ll / 128, 2, Bb), blk, MMA_SMEM>>>(q_b, k_b);

    // energy on tensor cores -> attention region, softmax in place
    energy_mma_kernel<<<dim3(Ll / 128, Ll / 128, Bb), blk, MMA_SMEM>>>(att_ptr);
    softmax_kernel<<<dim3(Bb * Ll), blk>>>(att_ptr);

    // out path: gamma==0 -> copy; gamma!=0 -> v conv + out GEMM
    copy_x_kernel<<<dim3((unsigned)(BCL / (256 * 4))), blk>>>(x, out_ptr, gamma);
    vconv_kernel<<<dim3(Ll / 128, Cc / 128, Bb), blk>>>(v_w, v_b, x, vbuf, gamma);
    outgemm_kernel<<<dim3(Ll / 128, Cc / 128, Bb), blk>>>(att_ptr, x, out_ptr, gamma);
}

// round 10
// speedup vs baseline: 2.3119x; 1.1378x over previous
#include <cuda_runtime.h>
#include <cuda_bf16.h>
#include <stdint.h>
#include <math.h>

#define Bb 8
#define Cc 512
#define Ll 2048
#define CQq 128

// Static device scratch (allocation-free rule: __device__ globals).
__device__ __nv_bfloat16 g_xhi[(size_t)Bb * Ll * Cc];    // x^T split hi [b][pos][c]
__device__ __nv_bfloat16 g_xlo[(size_t)Bb * Ll * Cc];
__device__ __nv_bfloat16 g_wqhi[CQq * Cc];
__device__ __nv_bfloat16 g_wqlo[CQq * Cc];
__device__ __nv_bfloat16 g_wkhi[CQq * Cc];
__device__ __nv_bfloat16 g_wklo[CQq * Cc];
__device__ __nv_bfloat16 g_qhi[(size_t)Bb * Ll * CQq];   // [b][pos][d]
__device__ __nv_bfloat16 g_qlo[(size_t)Bb * Ll * CQq];
__device__ __nv_bfloat16 g_khi[(size_t)Bb * Ll * CQq];
__device__ __nv_bfloat16 g_klo[(size_t)Bb * Ll * CQq];
__device__ float g_v[(size_t)Bb * Cc * Ll];              // gamma!=0 path only
__device__ float g_att[(size_t)Bb * Ll * Ll];            // fallback
__device__ float g_outbuf[(size_t)Bb * Cc * Ll];         // fallback

// smem tile pitch for 64-wide bf16 chunks: 72 -> word stride 36 -> ldmatrix
// 8-row x 16B reads cover all 32 banks exactly once (conflict-free).
#define CPAD 72
#define TILE_HW (128 * CPAD)   // bf16 elements per tile

// ---------------------------------------------------------------------------
// Split W (CQ x C fp32) into bf16 hi/lo. grid (128, 2), block 128.
// ---------------------------------------------------------------------------
__global__ __launch_bounds__(128)
void wsplit_kernel(const float* __restrict__ q_w, const float* __restrict__ k_w)
{
    const int row = blockIdx.x;
    const int s   = blockIdx.y;
    const float* W = s ? k_w : q_w;
    __nv_bfloat16* ho = s ? g_wkhi : g_wqhi;
    __nv_bfloat16* lo = s ? g_wklo : g_wqlo;

    const int c = threadIdx.x * 4;
    float4 v = *(const float4*)&W[(size_t)row * Cc + c];
    __nv_bfloat16 h[4], l[4];
    float vv[4] = {v.x, v.y, v.z, v.w};
    #pragma unroll
    for (int i = 0; i < 4; i++) {
        h[i] = __float2bfloat16_rn(vv[i]);
        l[i] = __float2bfloat16_rn(vv[i] - __bfloat162float(h[i]));
    }
    *(uint2*)&ho[(size_t)row * Cc + c] = *(uint2*)h;
    *(uint2*)&lo[(size_t)row * Cc + c] = *(uint2*)l;
}

// ---------------------------------------------------------------------------
// Transpose + split x: [b][c][l] fp32 -> [b][l][c] bf16 hi/lo.
// ---------------------------------------------------------------------------
__global__ __launch_bounds__(256)
void xsplit_kernel(const float* __restrict__ x)
{
    __shared__ float ts[64][65];
    const int b  = blockIdx.z;
    const int l0 = blockIdx.x * 64;
    const int c0 = blockIdx.y * 64;
    const int tid = threadIdx.x;

    const float* xb = x + (size_t)b * Cc * Ll;
    const int ly = tid >> 4;          // 0..15
    const int lx = (tid & 15) * 4;    // 0..60
    #pragma unroll
    for (int rr = 0; rr < 4; rr++) {
        const int cl = ly + rr * 16;
        float4 v = *(const float4*)&xb[(size_t)(c0 + cl) * Ll + l0 + lx];
        ts[cl][lx + 0] = v.x;
        ts[cl][lx + 1] = v.y;
        ts[cl][lx + 2] = v.z;
        ts[cl][lx + 3] = v.w;
    }
    __syncthreads();

    __nv_bfloat16* xh = g_xhi + (size_t)b * Ll * Cc;
    __nv_bfloat16* xl = g_xlo + (size_t)b * Ll * Cc;
    const int wy = tid >> 3;          // 0..31
    const int wx = (tid & 7) * 8;     // 0..56
    #pragma unroll
    for (int rr = 0; rr < 2; rr++) {
        const int ll = wy + rr * 32;
        __nv_bfloat16 h[8], l[8];
        #pragma unroll
        for (int e = 0; e < 8; e++) {
            float v = ts[wx + e][ll];
            h[e] = __float2bfloat16_rn(v);
            l[e] = __float2bfloat16_rn(v - __bfloat162float(h[e]));
        }
        *(uint4*)&xh[(size_t)(l0 + ll) * Cc + c0 + wx] = *(uint4*)h;
        *(uint4*)&xl[(size_t)(l0 + ll) * Cc + c0 + wx] = *(uint4*)l;
    }
}

// ---------------------------------------------------------------------------
// mma / ldmatrix helpers
// ---------------------------------------------------------------------------
__device__ __forceinline__ void mma16816(float* acc, const uint32_t* a,
                                         const uint32_t* bfr)
{
    asm volatile(
        "mma.sync.aligned.m16n8k16.row.col.f32.bf16.bf16.f32 "
        "{%0,%1,%2,%3}, {%4,%5,%6,%7}, {%8,%9}, {%0,%1,%2,%3};\n"
        : "+f"(acc[0]), "+f"(acc[1]), "+f"(acc[2]), "+f"(acc[3])
        : "r"(a[0]), "r"(a[1]), "r"(a[2]), "r"(a[3]),
          "r"(bfr[0]), "r"(bfr[1]));
}

__device__ __forceinline__ void ldsm_x4(uint32_t* r, uint32_t addr)
{
    asm volatile(
        "ldmatrix.sync.aligned.m8n8.x4.shared.b16 {%0,%1,%2,%3}, [%4];\n"
        : "=r"(r[0]), "=r"(r[1]), "=r"(r[2]), "=r"(r[3]) : "r"(addr));
}

// ---------------------------------------------------------------------------
// Shared inner compute: one 64-wide K chunk, 3-combo split bf16, ldmatrix.
// A tiles (Ahi/Alo) rows = output-m, B tiles (Bhi/Blo) rows = output-n.
// a_off/b_off are per-lane ldmatrix base offsets (bf16-element units).
// ---------------------------------------------------------------------------
__device__ __forceinline__ void kchunk_mma(
    uint32_t AhiU, uint32_t AloU, uint32_t BhiU, uint32_t BloU,
    uint32_t a_off, uint32_t b_off, float acc[4][4][4])
{
    #pragma unroll
    for (int ks = 0; ks < 4; ks++) {
        const int k0 = ks * 16;
        uint32_t bh[2][4], bl[2][4];   // [pair p][4 regs = bn=2p, 2p+1]
        #pragma unroll
        for (int p = 0; p < 2; p++) {
            const uint32_t bo = 2u * (b_off + (uint32_t)(p * 16 * CPAD + k0));
            ldsm_x4(bh[p], BhiU + bo);
            ldsm_x4(bl[p], BloU + bo);
        }
        #pragma unroll
        for (int am = 0; am < 4; am++) {
            const uint32_t ao = 2u * (a_off + (uint32_t)(am * 16 * CPAD + k0));
            uint32_t ah[4], al[4];
            ldsm_x4(ah, AhiU + ao);
            ldsm_x4(al, AloU + ao);
            #pragma unroll
            for (int bn = 0; bn < 4; bn++) {
                const uint32_t* bhp = &bh[bn >> 1][(bn & 1) * 2];
                const uint32_t* blp = &bl[bn >> 1][(bn & 1) * 2];
                mma16816(acc[am][bn], ah, bhp);
                mma16816(acc[am][bn], ah, blp);
                mma16816(acc[am][bn], al, bhp);
            }
        }
    }
}

// per-lane ldmatrix offsets (element units, relative to tile base)
__device__ __forceinline__ uint32_t a_frag_off(int wm, int lane)
{
    return (uint32_t)((wm * 64 + (lane & 15)) * CPAD + ((lane >> 4) << 3));
}
__device__ __forceinline__ uint32_t b_frag_off(int wn, int lane)
{
    return (uint32_t)((wn * 32 + ((lane >> 4) << 3) + (lane & 7)) * CPAD
                      + (((lane >> 3) & 1) << 3));
}

// ---------------------------------------------------------------------------
// q/k conv on tensor cores, split-bf16 3-combo:
//   out[pos][d] = sum_c xT[pos][c] * W[d][c] + bias[d]
// grid (L/128, 2 {q,k}, B), block 256 (8 warps, 2m x 4n), K=512 in 8 chunks.
// ---------------------------------------------------------------------------
__global__ __launch_bounds__(256, 2)
void qkconv_mma_kernel(const float* __restrict__ q_b, const float* __restrict__ k_b)
{
    extern __shared__ __nv_bfloat16 sm[];
    __nv_bfloat16* Ahi = sm;
    __nv_bfloat16* Alo = sm + TILE_HW;
    __nv_bfloat16* Bhi = sm + 2 * TILE_HW;
    __nv_bfloat16* Blo = sm + 3 * TILE_HW;
    __shared__ float sbias[128];

    const int p0 = blockIdx.x * 128;
    const int s  = blockIdx.y;
    const int b  = blockIdx.z;

    const __nv_bfloat16* whi = s ? g_wkhi : g_wqhi;
    const __nv_bfloat16* wlo = s ? g_wklo : g_wqlo;
    const float* bias = s ? k_b : q_b;

    const int tid  = threadIdx.x;
    const int lane = tid & 31;
    const int wid  = tid >> 5;
    const int wm   = wid >> 2;
    const int wn   = wid & 3;
    const int g    = lane >> 2;
    const int t    = lane & 3;

    if (tid < 128) sbias[tid] = bias[tid];

    const uint32_t AhiU = (uint32_t)__cvta_generic_to_shared(Ahi);
    const uint32_t AloU = (uint32_t)__cvta_generic_to_shared(Alo);
    const uint32_t BhiU = (uint32_t)__cvta_generic_to_shared(Bhi);
    const uint32_t BloU = (uint32_t)__cvta_generic_to_shared(Blo);
    const uint32_t a_off = a_frag_off(wm, lane);
    const uint32_t b_off = b_frag_off(wn, lane);

    const __nv_bfloat16* xh = g_xhi + (size_t)b * Ll * Cc;
    const __nv_bfloat16* xl = g_xlo + (size_t)b * Ll * Cc;

    float acc[4][4][4];
    #pragma unroll
    for (int am = 0; am < 4; am++)
        #pragma unroll
        for (int bn = 0; bn < 4; bn++)
            #pragma unroll
            for (int c = 0; c < 4; c++) acc[am][bn][c] = 0.0f;

    for (int it = 0; it < 8; it++) {
        const int c0 = it * 64;
        if (it) __syncthreads();
        #pragma unroll
        for (int q = 0; q < 4; q++) {
            const int idx = q * 256 + tid;
            const int r  = idx >> 3;
            const int cc = (idx & 7) * 8;
            *(uint4*)&Ahi[r * CPAD + cc] = *(const uint4*)&xh[(size_t)(p0 + r) * Cc + c0 + cc];
            *(uint4*)&Alo[r * CPAD + cc] = *(const uint4*)&xl[(size_t)(p0 + r) * Cc + c0 + cc];
            *(uint4*)&Bhi[r * CPAD + cc] = *(const uint4*)&whi[(size_t)r * Cc + c0 + cc];
            *(uint4*)&Blo[r * CPAD + cc] = *(const uint4*)&wlo[(size_t)r * Cc + c0 + cc];
        }
        __syncthreads();
        kchunk_mma(AhiU, AloU, BhiU, BloU, a_off, b_off, acc);
    }

    __nv_bfloat16* hb = (s ? g_khi : g_qhi) + (size_t)b * Ll * CQq;
    __nv_bfloat16* lb = (s ? g_klo : g_qlo) + (size_t)b * Ll * CQq;
    #pragma unroll
    for (int am = 0; am < 4; am++) {
        const int r0 = wm * 64 + am * 16 + g;
        #pragma unroll
        for (int bn = 0; bn < 4; bn++) {
            const int col = wn * 32 + bn * 8 + 2 * t;
            const float b0 = sbias[col], b1 = sbias[col + 1];
            #pragma unroll
            for (int half = 0; half < 2; half++) {
                const int row = r0 + half * 8;
                const float v0 = acc[am][bn][half * 2 + 0] + b0;
                const float v1 = acc[am][bn][half * 2 + 1] + b1;
                __nv_bfloat16 h0 = __float2bfloat16_rn(v0);
                __nv_bfloat16 h1 = __float2bfloat16_rn(v1);
                __nv_bfloat16 l0 = __float2bfloat16_rn(v0 - __bfloat162float(h0));
                __nv_bfloat16 l1 = __float2bfloat16_rn(v1 - __bfloat162float(h1));
                *(__nv_bfloat162*)&hb[(size_t)(p0 + row) * CQq + col] =
                    __halves2bfloat162(h0, h1);
                *(__nv_bfloat162*)&lb[(size_t)(p0 + row) * CQq + col] =
                    __halves2bfloat162(l0, l1);
            }
        }
    }
}

// ---------------------------------------------------------------------------
// energy[b,i,j] = sum_d q[b,i,d]*k[b,j,d], split-bf16 3-combo, ldmatrix frags.
// K=128 in 2 chunks of 64.
// ---------------------------------------------------------------------------
__global__ __launch_bounds__(256, 2)
void energy_mma_kernel(float* __restrict__ E)
{
    extern __shared__ __nv_bfloat16 sm[];
    __nv_bfloat16* Ahi = sm;
    __nv_bfloat16* Alo = sm + TILE_HW;
    __nv_bfloat16* Bhi = sm + 2 * TILE_HW;
    __nv_bfloat16* Blo = sm + 3 * TILE_HW;

    const int b  = blockIdx.z;
    const int i0 = blockIdx.y * 128;
    const int j0 = blockIdx.x * 128;

    const int tid  = threadIdx.x;
    const int lane = tid & 31;
    const int wid  = tid >> 5;
    const int wm   = wid >> 2;
    const int wn   = wid & 3;
    const int g    = lane >> 2;
    const int t    = lane & 3;

    const uint32_t AhiU = (uint32_t)__cvta_generic_to_shared(Ahi);
    const uint32_t AloU = (uint32_t)__cvta_generic_to_shared(Alo);
    const uint32_t BhiU = (uint32_t)__cvta_generic_to_shared(Bhi);
    const uint32_t BloU = (uint32_t)__cvta_generic_to_shared(Blo);
    const uint32_t a_off = a_frag_off(wm, lane);
    const uint32_t b_off = b_frag_off(wn, lane);

    const size_t boff = (size_t)b * Ll * CQq;
    const __nv_bfloat16* qh = g_qhi + boff;
    const __nv_bfloat16* ql = g_qlo + boff;
    const __nv_bfloat16* kh = g_khi + boff;
    const __nv_bfloat16* kl = g_klo + boff;

    float acc[4][4][4];
    #pragma unroll
    for (int am = 0; am < 4; am++)
        #pragma unroll
        for (int bn = 0; bn < 4; bn++)
            #pragma unroll
            for (int c = 0; c < 4; c++) acc[am][bn][c] = 0.0f;

    #pragma unroll
    for (int it = 0; it < 2; it++) {
        const int c0 = it * 64;
        if (it) __syncthreads();
        #pragma unroll
        for (int q = 0; q < 4; q++) {
            const int idx = q * 256 + tid;
            const int r  = idx >> 3;
            const int cc = (idx & 7) * 8;
            *(uint4*)&Ahi[r * CPAD + cc] = *(const uint4*)&qh[(size_t)(i0 + r) * CQq + c0 + cc];
            *(uint4*)&Alo[r * CPAD + cc] = *(const uint4*)&ql[(size_t)(i0 + r) * CQq + c0 + cc];
            *(uint4*)&Bhi[r * CPAD + cc] = *(const uint4*)&kh[(size_t)(j0 + r) * CQq + c0 + cc];
            *(uint4*)&Blo[r * CPAD + cc] = *(const uint4*)&kl[(size_t)(j0 + r) * CQq + c0 + cc];
        }
        __syncthreads();
        kchunk_mma(AhiU, AloU, BhiU, BloU, a_off, b_off, acc);
    }

    float* eb = E + (size_t)b * Ll * Ll;
    #pragma unroll
    for (int am = 0; am < 4; am++) {
        const int row = i0 + wm * 64 + am * 16 + g;
        #pragma unroll
        for (int bn = 0; bn < 4; bn++) {
            const int col = j0 + wn * 32 + bn * 8 + 2 * t;
            *(float2*)&eb[(size_t)row * Ll + col] =
                make_float2(acc[am][bn][0], acc[am][bn][1]);
            *(float2*)&eb[(size_t)(row + 8) * Ll + col] =
                make_float2(acc[am][bn][2], acc[am][bn][3]);
        }
    }
}

// ---------------------------------------------------------------------------
// In-place row softmax, float4 loads + warp-shuffle reductions.
// ---------------------------------------------------------------------------
__global__ __launch_bounds__(256)
void softmax_kernel(float* __restrict__ att)
{
    const size_t row = blockIdx.x;
    float4* p = (float4*)(att + row * (size_t)Ll);
    const int tid = threadIdx.x;
    const int lane = tid & 31, wrp = tid >> 5;

    float4 v0 = p[tid];
    float4 v1 = p[tid + 256];

    float m = fmaxf(fmaxf(fmaxf(v0.x, v0.y), fmaxf(v0.z, v0.w)),
                    fmaxf(fmaxf(v1.x, v1.y), fmaxf(v1.z, v1.w)));
    #pragma unroll
    for (int s = 16; s > 0; s >>= 1)
        m = fmaxf(m, __shfl_xor_sync(0xffffffffu, m, s));

    __shared__ float red[8];
    if (lane == 0) red[wrp] = m;
    __syncthreads();
    float bm = red[lane & 7];
    #pragma unroll
    for (int s = 4; s > 0; s >>= 1)
        bm = fmaxf(bm, __shfl_xor_sync(0xffffffffu, bm, s));
    m = __shfl_sync(0xffffffffu, bm, 0);

    v0.x = __expf(v0.x - m); v0.y = __expf(v0.y - m);
    v0.z = __expf(v0.z - m); v0.w = __expf(v0.w - m);
    v1.x = __expf(v1.x - m); v1.y = __expf(v1.y - m);
    v1.z = __expf(v1.z - m); v1.w = __expf(v1.w - m);

    float sum = v0.x + v0.y + v0.z + v0.w + v1.x + v1.y + v1.z + v1.w;
    #pragma unroll
    for (int s = 16; s > 0; s >>= 1)
        sum += __shfl_xor_sync(0xffffffffu, sum, s);
    __syncthreads();
    if (lane == 0) red[wrp] = sum;
    __syncthreads();
    float bs = red[lane & 7];
    #pragma unroll
    for (int s = 4; s > 0; s >>= 1)
        bs += __shfl_xor_sync(0xffffffffu, bs, s);
    const float inv = 1.0f / __shfl_sync(0xffffffffu, bs, 0);

    v0.x *= inv; v0.y *= inv; v0.z *= inv; v0.w *= inv;
    v1.x *= inv; v1.y *= inv; v1.z *= inv; v1.w *= inv;
    p[tid]       = v0;
    p[tid + 256] = v1;
}

// ---------------------------------------------------------------------------
// gamma == 0 fast path: out = x. Gated on gamma[0]==0.
// ---------------------------------------------------------------------------
__global__ __launch_bounds__(256)
void copy_x_kernel(const float* __restrict__ x, float* __restrict__ out,
                   const float* __restrict__ gamma)
{
    if (gamma[0] != 0.0f) return;
    const size_t idx = ((size_t)blockIdx.x * 256 + threadIdx.x) * 4;
    *(float4*)&out[idx] = *(const float4*)&x[idx];
}

// ---------------------------------------------------------------------------
// gamma != 0 path kernels (gated; full-precision fallback).
// ---------------------------------------------------------------------------
__global__ __launch_bounds__(256)
void vconv_kernel(const float* __restrict__ W, const float* __restrict__ bias,
                  const float* __restrict__ x, float* __restrict__ out,
                  const float* __restrict__ gamma)
{
    if (gamma[0] == 0.0f) return;
    const int b  = blockIdx.z;
    const int m0 = blockIdx.y * 128;
    const int n0 = blockIdx.x * 128;

    __shared__ float As[8][128];
    __shared__ float Bs[8][128];

    const int tid = threadIdx.x;
    const int tx = tid % 16, ty = tid / 16;
    const float* xb = x + (size_t)b * Cc * Ll;

    const int aRow = tid >> 1;
    const int aCol = (tid & 1) * 4;
    const int bRow = tid >> 5;
    const int bCol = (tid & 31) * 4;

    float acc[8][8];
    #pragma unroll
    for (int i = 0; i < 8; i++)
        #pragma unroll
        for (int j = 0; j < 8; j++) acc[i][j] = 0.0f;

    for (int k0 = 0; k0 < Cc; k0 += 8) {
        float4 a = *(const float4*)&W[(size_t)(m0 + aRow) * Cc + k0 + aCol];
        As[aCol + 0][aRow] = a.x;
        As[aCol + 1][aRow] = a.y;
        As[aCol + 2][aRow] = a.z;
        As[aCol + 3][aRow] = a.w;
        *(float4*)&Bs[bRow][bCol] =
            *(const float4*)&xb[(size_t)(k0 + bRow) * Ll + n0 + bCol];
        __syncthreads();

        #pragma unroll
        for (int k = 0; k < 8; k++) {
            float rm[8], rn[8];
            #pragma unroll
            for (int i = 0; i < 8; i++) rm[i] = As[k][ty * 8 + i];
            #pragma unroll
            for (int j = 0; j < 8; j++) rn[j] = Bs[k][tx * 8 + j];
            #pragma unroll
            for (int i = 0; i < 8; i++)
                #pragma unroll
                for (int j = 0; j < 8; j++)
                    acc[i][j] = fmaf(rm[i], rn[j], acc[i][j]);
        }
        __syncthreads();
    }

    float* ob = out + (size_t)b * Cc * Ll;
    #pragma unroll
    for (int i = 0; i < 8; i++) {
        const int m = m0 + ty * 8 + i;
        const float bb = bias[m];
        float* po = ob + (size_t)m * Ll + n0 + tx * 8;
        *(float4*)po = make_float4(acc[i][0] + bb, acc[i][1] + bb,
                                   acc[i][2] + bb, acc[i][3] + bb);
        *(float4*)(po + 4) = make_float4(acc[i][4] + bb, acc[i][5] + bb,
                                         acc[i][6] + bb, acc[i][7] + bb);
    }
}

__global__ __launch_bounds__(256)
void outgemm_kernel(const float* __restrict__ att, const float* __restrict__ x,
                    float* __restrict__ out, const float* __restrict__ gamma)
{
    const float g = gamma[0];
    if (g == 0.0f) return;
    const int b  = blockIdx.z;
    const int c0 = blockIdx.y * 128;
    const int i0 = blockIdx.x * 128;

    __shared__ float Vs[8][128];
    __shared__ float Ts[8][128];

    const int tid = threadIdx.x;
    const int tx = tid % 16, ty = tid / 16;
    const int aRow = tid >> 1;
    const int aCol = (tid & 1) * 4;

    const float* vb = g_v + (size_t)b * Cc * Ll;
    const float* ab = att + (size_t)b * Ll * Ll;

    float acc[8][8];
    #pragma unroll
    for (int i = 0; i < 8; i++)
        #pragma unroll
        for (int j = 0; j < 8; j++) acc[i][j] = 0.0f;

    for (int j0 = 0; j0 < Ll; j0 += 8) {
        float4 a = *(const float4*)&vb[(size_t)(c0 + aRow) * Ll + j0 + aCol];
        Vs[aCol + 0][aRow] = a.x;
        Vs[aCol + 1][aRow] = a.y;
        Vs[aCol + 2][aRow] = a.z;
        Vs[aCol + 3][aRow] = a.w;
        float4 tt = *(const float4*)&ab[(size_t)(i0 + aRow) * Ll + j0 + aCol];
        Ts[aCol + 0][aRow] = tt.x;
        Ts[aCol + 1][aRow] = tt.y;
        Ts[aCol + 2][aRow] = tt.z;
        Ts[aCol + 3][aRow] = tt.w;
        __syncthreads();

        #pragma unroll
        for (int k = 0; k < 8; k++) {
            float rm[8], rn[8];
            #pragma unroll
            for (int i = 0; i < 8; i++) rm[i] = Vs[k][ty * 8 + i];
            #pragma unroll
            for (int j = 0; j < 8; j++) rn[j] = Ts[k][tx * 8 + j];
            #pragma unroll
            for (int i = 0; i < 8; i++)
                #pragma unroll
                for (int j = 0; j < 8; j++)
                    acc[i][j] = fmaf(rm[i], rn[j], acc[i][j]);
        }
        __syncthreads();
    }

    #pragma unroll
    for (int i = 0; i < 8; i++) {
        const size_t off = (size_t)b * Cc * Ll + (size_t)(c0 + ty * 8 + i) * Ll
                         + i0 + tx * 8;
        #pragma unroll
        for (int j = 0; j < 8; j++)
            out[off + j] = g * acc[i][j] + x[off + j];
    }
}

// ---------------------------------------------------------------------------
extern "C" void kernel_launch(void* const* d_in, const int* in_sizes, int n_in,
                              void* d_out, int out_size)
{
    (void)in_sizes; (void)n_in;
    const float* x     = (const float*)d_in[0];
    const float* q_w   = (const float*)d_in[1];
    const float* q_b   = (const float*)d_in[2];
    const float* k_w   = (const float*)d_in[3];
    const float* k_b   = (const float*)d_in[4];
    const float* v_w   = (const float*)d_in[5];
    const float* v_b   = (const float*)d_in[6];
    const float* gamma = (const float*)d_in[7];

    const size_t BCL = (size_t)Bb * Cc * Ll;        // 8388608
    const size_t BLL = (size_t)Bb * Ll * Ll;        // 33554432

    float* out_ptr;
    float* att_ptr;
    if ((size_t)out_size >= BCL + BLL) {
        out_ptr = (float*)d_out;
        att_ptr = (float*)d_out + BCL;
    } else if ((size_t)out_size == BLL) {
        cudaGetSymbolAddress((void**)&out_ptr, g_outbuf);
        att_ptr = (float*)d_out;
    } else {
        out_ptr = (float*)d_out;
        cudaGetSymbolAddress((void**)&att_ptr, g_att);
    }
    float* vbuf; cudaGetSymbolAddress((void**)&vbuf, g_v);

    static int smem_set = 0;
    const int MMA_SMEM = 4 * TILE_HW * (int)sizeof(__nv_bfloat16); // 73728
    if (!smem_set) {
        cudaFuncSetAttribute(energy_mma_kernel,
                             cudaFuncAttributeMaxDynamicSharedMemorySize,
                             MMA_SMEM);
        cudaFuncSetAttribute(qkconv_mma_kernel,
                             cudaFuncAttributeMaxDynamicSharedMemorySize,
                             MMA_SMEM);
        smem_set = 1;
    }

    dim3 blk(256);

    // split inputs for tensor-core path
    wsplit_kernel<<<dim3(CQq, 2), dim3(128)>>>(q_w, k_w);
    xsplit_kernel<<<dim3(Ll / 64, Cc / 64, Bb), blk>>>(x);

    // q and k projections on tensor cores -> split bf16 [pos][d]
    qkconv_mma_kernel<<<dim3(Ll / 128, 2, Bb), blk, MMA_SMEM>>>(q_b, k_b);

    // energy on tensor cores -> attention region, softmax in place
    energy_mma_kernel<<<dim3(Ll / 128, Ll / 128, Bb), blk, MMA_SMEM>>>(att_ptr);
    softmax_kernel<<<dim3(Bb * Ll), blk>>>(att_ptr);

    // out path: gamma==0 -> copy; gamma!=0 -> v conv + out GEMM
    copy_x_kernel<<<dim3((unsigned)(BCL / (256 * 4))), blk>>>(x, out_ptr, gamma);
    vconv_kernel<<<dim3(Ll / 128, Cc / 128, Bb), blk>>>(v_w, v_b, x, vbuf, gamma);
    outgemm_kernel<<<dim3(Ll / 128, Cc / 128, Bb), blk>>>(att_ptr, x, out_ptr, gamma);
}